// round 3
// baseline (speedup 1.0000x reference)
#include <cuda_runtime.h>
#include <cstddef>

typedef unsigned long long ull;

#define Nn   512
#define IND  256
#define HIDD 256
#define AH   128
#define OUTD 256
#define WELD 262   // IN_DIM + 6

// ---------------- scratch ----------------
__device__ float g_F[Nn * HIDD];
__device__ float g_q[Nn * AH];
__device__ float g_qk[Nn * HIDD];
__device__ float g_w[Nn * HIDD];
__device__ float g_agg[Nn * HIDD];

// ---------------- f32x2 helpers ----------------
__device__ __forceinline__ ull pack2(float lo, float hi) {
    ull r; asm("mov.b64 %0,{%1,%2};" : "=l"(r) : "f"(lo), "f"(hi)); return r;
}
__device__ __forceinline__ float2 unp2(ull x) {
    float2 f; asm("mov.b64 {%0,%1},%2;" : "=f"(f.x), "=f"(f.y) : "l"(x)); return f;
}
__device__ __forceinline__ ull fma2(ull a, ull b, ull c) {
    ull d; asm("fma.rn.f32x2 %0,%1,%2,%3;" : "=l"(d) : "l"(a), "l"(b), "l"(c)); return d;
}
__device__ __forceinline__ ull mul2(ull a, ull b) {
    ull d; asm("mul.rn.f32x2 %0,%1,%2;" : "=l"(d) : "l"(a), "l"(b)); return d;
}
__device__ __forceinline__ ull relu2(ull x) {
    ull r;
    asm("{.reg .f32 lo,hi;\n\t"
        "mov.b64 {lo,hi},%1;\n\t"
        "max.f32 lo,lo,0f00000000;\n\t"
        "max.f32 hi,hi,0f00000000;\n\t"
        "mov.b64 %0,{lo,hi};}" : "=l"(r) : "l"(x));
    return r;
}

// ---------------- small fp32 GEMM ----------------
template <bool TRANSB, bool ACCUM, bool RELU>
__global__ __launch_bounds__(256) void gemm_k(
    const float* __restrict__ A, int lda,
    const float* __restrict__ B, int ldb,
    const float* __restrict__ bias,
    float* __restrict__ C, int ldc,
    int K, float alpha)
{
    __shared__ float As[32][34];
    __shared__ float Bs[32][34];
    const int t = threadIdx.x;
    const int tx = t & 15, ty = t >> 4;
    const int mb = blockIdx.y * 32, nb = blockIdx.x * 32;
    float a00 = 0.f, a01 = 0.f, a10 = 0.f, a11 = 0.f;

    for (int k0 = 0; k0 < K; k0 += 32) {
#pragma unroll
        for (int r = 0; r < 4; r++) {
            int idx = t + r * 256;
            int p = idx >> 5, s = idx & 31;
            As[s][p] = A[(size_t)(mb + p) * lda + (k0 + s)];
            if (TRANSB)
                Bs[s][p] = B[(size_t)(nb + p) * ldb + (k0 + s)];
            else
                Bs[p][s] = B[(size_t)(k0 + p) * ldb + (nb + s)];
        }
        __syncthreads();
#pragma unroll
        for (int kk = 0; kk < 32; kk++) {
            float2 av = *(const float2*)&As[kk][ty * 2];
            float2 bv = *(const float2*)&Bs[kk][tx * 2];
            a00 = fmaf(av.x, bv.x, a00);
            a01 = fmaf(av.x, bv.y, a01);
            a10 = fmaf(av.y, bv.x, a10);
            a11 = fmaf(av.y, bv.y, a11);
        }
        __syncthreads();
    }

    int m = mb + ty * 2, n = nb + tx * 2;
    float b0 = bias ? bias[n] : 0.f;
    float b1 = bias ? bias[n + 1] : 0.f;
    float v00 = fmaf(alpha, a00, b0), v01 = fmaf(alpha, a01, b1);
    float v10 = fmaf(alpha, a10, b0), v11 = fmaf(alpha, a11, b1);
    if (ACCUM) {
        v00 += C[(size_t)m * ldc + n];
        v01 += C[(size_t)m * ldc + n + 1];
        v10 += C[(size_t)(m + 1) * ldc + n];
        v11 += C[(size_t)(m + 1) * ldc + n + 1];
    }
    if (RELU) {
        v00 = fmaxf(v00, 0.f); v01 = fmaxf(v01, 0.f);
        v10 = fmaxf(v10, 0.f); v11 = fmaxf(v11, 0.f);
    }
    C[(size_t)m * ldc + n]           = v00;
    C[(size_t)m * ldc + n + 1]       = v01;
    C[(size_t)(m + 1) * ldc + n]     = v10;
    C[(size_t)(m + 1) * ldc + n + 1] = v11;
}

// ================ fused attention: one block per row i =====================
// w[i,h] = (1/l) * sum_j exp(s_ij) * relu(F[j,h] + edges[i,j]·We[h,:6])
// s_ij   = sum_h qk[i,h] * E[i,j,h]   (qk pre-scaled; diag excluded)
// Thread t: hp = t&127 owns h-pair (2hp, 2hp+1); grp = t>>7 owns half the jj.
// E tile lives only in registers (computed once, used for score + aggregation).
__global__ __launch_bounds__(256) void fused_attn_k(
    const float* __restrict__ edges,
    const float* __restrict__ We,
    const float* __restrict__ Fm,
    const float* __restrict__ qkm,
    float* __restrict__ wout)
{
    __shared__ __align__(16) float e16[32][16];   // edge feats, duplicated per pair
    __shared__ float sP[128 * 33];                // per-(hp,jj) score partials
    __shared__ float sQ[8 * 33];                  // per-(k,jj) partials
    __shared__ ull   p2[32];                      // exp(s) duplicated lanes
    __shared__ ull   wtmp[128];
    __shared__ float l_s;

    const int t = threadIdx.x;
    const int hp = t & 127, grp = t >> 7;
    const int i = blockIdx.x;

    ull W2[6];
#pragma unroll
    for (int c = 0; c < 6; c++)
        W2[c] = pack2(We[(size_t)(2 * hp) * WELD + c],
                      We[(size_t)(2 * hp + 1) * WELD + c]);
    const ull qk2 = *(const ull*)(qkm + (size_t)i * HIDD + 2 * hp);
    ull w2 = pack2(0.f, 0.f);
    if (t == 0) l_s = 0.f;

    for (int tile = 0; tile < 16; tile++) {
        const int j0 = tile * 32;
        __syncthreads();                           // protect smem from prev tile
        if (t < 192) {                             // stage 32x6 edge feats (dup)
            int jj = t / 6, c = t - jj * 6;
            float v = edges[((size_t)i * Nn + (j0 + jj)) * 6 + c];
            e16[jj][2 * c]     = v;
            e16[jj][2 * c + 1] = v;
        }
        __syncthreads();

        // ---- build E tile in registers + score partials ----
        ull E2[16];
#pragma unroll
        for (int jj8 = 0; jj8 < 16; jj8++) {
            const int jj = 2 * jj8 + grp;
            ull F2 = *(const ull*)(Fm + (size_t)(j0 + jj) * HIDD + 2 * hp);
            const ulonglong2* ev = (const ulonglong2*)&e16[jj][0];
            ulonglong2 eA = ev[0], eB = ev[1], eC = ev[2];
            ull g = fma2(eA.x, W2[0], F2);
            g = fma2(eA.y, W2[1], g);
            g = fma2(eB.x, W2[2], g);
            g = fma2(eB.y, W2[3], g);
            g = fma2(eC.x, W2[4], g);
            g = fma2(eC.y, W2[5], g);
            g = relu2(g);
            E2[jj8] = g;
            float2 d = unp2(mul2(qk2, g));
            sP[hp * 33 + jj] = d.x + d.y;
        }
        __syncthreads();

        // ---- two-step conflict-free reduction over hp ----
        {
            int jj = t & 31, k = t >> 5;
            float s = 0.f;
#pragma unroll
            for (int m = 0; m < 16; m++)
                s += sP[(k * 16 + m) * 33 + jj];
            sQ[k * 33 + jj] = s;
        }
        __syncthreads();
        if (t < 32) {
            float s = 0.f;
#pragma unroll
            for (int k = 0; k < 8; k++)
                s += sQ[k * 33 + t];
            float p = (j0 + t == i) ? 0.f : __expf(s);
            p2[t] = pack2(p, p);
#pragma unroll
            for (int o = 16; o; o >>= 1)
                p += __shfl_xor_sync(0xffffffffu, p, o);
            if (t == 0) l_s += p;
        }
        __syncthreads();

        // ---- aggregate: w2 += p * E (E still in registers) ----
#pragma unroll
        for (int jj8 = 0; jj8 < 16; jj8++)
            w2 = fma2(p2[2 * jj8 + grp], E2[jj8], w2);
    }

    __syncthreads();
    if (grp == 1) wtmp[hp] = w2;
    __syncthreads();
    if (grp == 0) {
        float2 a = unp2(w2), b = unp2(wtmp[hp]);
        float inv = 1.f / l_s;
        float2 r = make_float2((a.x + b.x) * inv, (a.y + b.y) * inv);
        *(float2*)(wout + (size_t)i * HIDD + 2 * hp) = r;
    }
}

// ---------------- launch ----------------
extern "C" void kernel_launch(void* const* d_in, const int* in_sizes, int n_in,
                              void* d_out, int out_size)
{
    const float* app   = (const float*)d_in[0];
    const float* edges = (const float*)d_in[1];
    const float* We    = (const float*)d_in[2];
    const float* be    = (const float*)d_in[3];
    const float* Wq    = (const float*)d_in[4];
    const float* bq    = (const float*)d_in[5];
    const float* Wk    = (const float*)d_in[6];
    // d_in[7] = bk: per-row constant in S -> cancels in softmax
    const float* Wv    = (const float*)d_in[8];
    const float* bv    = (const float*)d_in[9];
    const float* Wo    = (const float*)d_in[10];
    const float* bo    = (const float*)d_in[11];
    float* out = (float*)d_out;

    float *F, *q, *qk, *w, *agg;
    cudaGetSymbolAddress((void**)&F,   g_F);
    cudaGetSymbolAddress((void**)&q,   g_q);
    cudaGetSymbolAddress((void**)&qk,  g_qk);
    cudaGetSymbolAddress((void**)&w,   g_w);
    cudaGetSymbolAddress((void**)&agg, g_agg);

    // F = app @ We[:,6:]^T + be
    gemm_k<true, false, false><<<dim3(HIDD / 32, Nn / 32), 256>>>(
        app, IND, We + 6, WELD, be, F, HIDD, IND, 1.f);
    // q = app @ Wq^T + bq
    gemm_k<true, false, false><<<dim3(AH / 32, Nn / 32), 256>>>(
        app, IND, Wq, IND, bq, q, AH, IND, 1.f);
    // qk = (q @ Wk) / sqrt(128)
    gemm_k<false, false, false><<<dim3(HIDD / 32, Nn / 32), 256>>>(
        q, AH, Wk, HIDD, nullptr, qk, HIDD, AH, 0.08838834764831845f);

    // fused: E build + scores + softmax + aggregation, one block per row
    fused_attn_k<<<Nn, 256>>>(edges, We, F, qk, w);

    // agg = w @ Wv^T + bv
    gemm_k<true, false, false><<<dim3(HIDD / 32, Nn / 32), 256>>>(
        w, HIDD, Wv, HIDD, bv, agg, HIDD, HIDD, 1.f);
    // out = app @ Wo[:, :256]^T
    gemm_k<true, false, false><<<dim3(OUTD / 32, Nn / 32), 256>>>(
        app, IND, Wo, IND + HIDD, nullptr, out, OUTD, IND, 1.f);
    // out = ReLU(out + agg @ Wo[:, 256:]^T + bo)
    gemm_k<true, true, true><<<dim3(OUTD / 32, Nn / 32), 256>>>(
        agg, HIDD, Wo + IND, IND + HIDD, bo, out, OUTD, HIDD, 1.f);
}

// round 4
// speedup vs baseline: 1.1372x; 1.1372x over previous
#include <cuda_runtime.h>
#include <cstddef>

typedef unsigned long long ull;

#define Nn   512
#define IND  256
#define HIDD 256
#define AH   128
#define OUTD 256
#define WELD 262   // IN_DIM + 6
#define NPART 16   // passB j-partials

// ---------------- scratch ----------------
__device__ float g_F[Nn * HIDD];
__device__ float g_q[Nn * AH];
__device__ float g_qk[Nn * HIDD];
__device__ float g_S[Nn * Nn];
__device__ float g_wp[NPART * Nn * HIDD];
__device__ float g_w[Nn * HIDD];
__device__ float g_agg[Nn * HIDD];

// ---------------- f32x2 helpers ----------------
__device__ __forceinline__ ull pack2(float lo, float hi) {
    ull r; asm("mov.b64 %0,{%1,%2};" : "=l"(r) : "f"(lo), "f"(hi)); return r;
}
__device__ __forceinline__ float2 unp2(ull x) {
    float2 f; asm("mov.b64 {%0,%1},%2;" : "=f"(f.x), "=f"(f.y) : "l"(x)); return f;
}
__device__ __forceinline__ ull fma2(ull a, ull b, ull c) {
    ull d; asm("fma.rn.f32x2 %0,%1,%2,%3;" : "=l"(d) : "l"(a), "l"(b), "l"(c)); return d;
}
__device__ __forceinline__ ull relu2(ull x) {
    ull r;
    asm("{.reg .f32 lo,hi;\n\t"
        "mov.b64 {lo,hi},%1;\n\t"
        "max.f32 lo,lo,0f00000000;\n\t"
        "max.f32 hi,hi,0f00000000;\n\t"
        "mov.b64 %0,{lo,hi};}" : "=l"(r) : "l"(x));
    return r;
}

// ---------------- small fp32 GEMM ----------------
template <bool TRANSB>
__global__ __launch_bounds__(256) void gemm_k(
    const float* __restrict__ A, int lda,
    const float* __restrict__ B, int ldb,
    const float* __restrict__ bias,
    float* __restrict__ C, int ldc,
    int K, float alpha)
{
    __shared__ float As[32][34];
    __shared__ float Bs[32][34];
    const int t = threadIdx.x;
    const int tx = t & 15, ty = t >> 4;
    const int mb = blockIdx.y * 32, nb = blockIdx.x * 32;
    float a00 = 0.f, a01 = 0.f, a10 = 0.f, a11 = 0.f;

    for (int k0 = 0; k0 < K; k0 += 32) {
#pragma unroll
        for (int r = 0; r < 4; r++) {
            int idx = t + r * 256;
            int p = idx >> 5, s = idx & 31;
            As[s][p] = A[(size_t)(mb + p) * lda + (k0 + s)];
            if (TRANSB)
                Bs[s][p] = B[(size_t)(nb + p) * ldb + (k0 + s)];
            else
                Bs[p][s] = B[(size_t)(k0 + p) * ldb + (nb + s)];
        }
        __syncthreads();
#pragma unroll
        for (int kk = 0; kk < 32; kk++) {
            float2 av = *(const float2*)&As[kk][ty * 2];
            float2 bv = *(const float2*)&Bs[kk][tx * 2];
            a00 = fmaf(av.x, bv.x, a00);
            a01 = fmaf(av.x, bv.y, a01);
            a10 = fmaf(av.y, bv.x, a10);
            a11 = fmaf(av.y, bv.y, a11);
        }
        __syncthreads();
    }

    int m = mb + ty * 2, n = nb + tx * 2;
    float b0 = bias ? bias[n] : 0.f;
    float b1 = bias ? bias[n + 1] : 0.f;
    C[(size_t)m * ldc + n]           = fmaf(alpha, a00, b0);
    C[(size_t)m * ldc + n + 1]       = fmaf(alpha, a01, b1);
    C[(size_t)(m + 1) * ldc + n]     = fmaf(alpha, a10, b0);
    C[(size_t)(m + 1) * ldc + n + 1] = fmaf(alpha, a11, b1);
}

// ---------------- concat-K output GEMM: C = relu([A1|A2] @ B^T + bias) --------
__global__ __launch_bounds__(256) void gemm_cat2_k(
    const float* __restrict__ A1,
    const float* __restrict__ A2,
    const float* __restrict__ B,
    const float* __restrict__ bias,
    float* __restrict__ C)
{
    __shared__ float As[32][34];
    __shared__ float Bs[32][34];
    const int t = threadIdx.x;
    const int tx = t & 15, ty = t >> 4;
    const int mb = blockIdx.y * 32, nb = blockIdx.x * 32;
    float a00 = 0.f, a01 = 0.f, a10 = 0.f, a11 = 0.f;

    for (int k0 = 0; k0 < 512; k0 += 32) {
        const float* Asrc = (k0 < 256) ? A1 : A2;
        const int koff = (k0 < 256) ? k0 : k0 - 256;
#pragma unroll
        for (int r = 0; r < 4; r++) {
            int idx = t + r * 256;
            int p = idx >> 5, s = idx & 31;
            As[s][p] = Asrc[(size_t)(mb + p) * 256 + koff + s];
            Bs[s][p] = B[(size_t)(nb + p) * 512 + k0 + s];
        }
        __syncthreads();
#pragma unroll
        for (int kk = 0; kk < 32; kk++) {
            float2 av = *(const float2*)&As[kk][ty * 2];
            float2 bv = *(const float2*)&Bs[kk][tx * 2];
            a00 = fmaf(av.x, bv.x, a00);
            a01 = fmaf(av.x, bv.y, a01);
            a10 = fmaf(av.y, bv.x, a10);
            a11 = fmaf(av.y, bv.y, a11);
        }
        __syncthreads();
    }

    int m = mb + ty * 2, n = nb + tx * 2;
    float b0 = bias[n], b1 = bias[n + 1];
    C[(size_t)m * OUTD + n]           = fmaxf(a00 + b0, 0.f);
    C[(size_t)m * OUTD + n + 1]       = fmaxf(a01 + b1, 0.f);
    C[(size_t)(m + 1) * OUTD + n]     = fmaxf(a10 + b0, 0.f);
    C[(size_t)(m + 1) * OUTD + n + 1] = fmaxf(a11 + b1, 0.f);
}

// ---------------- pass A ----------------
#define PA_STR 130
__global__ __launch_bounds__(256) void passA_k(
    const float* __restrict__ edges,
    const float* __restrict__ We,
    const float* __restrict__ Fm,
    const float* __restrict__ qkm,
    float* __restrict__ S)
{
    __shared__ __align__(16) float WeP[2048];
    __shared__ float qs[32 * PA_STR];
    __shared__ float fs[32 * PA_STR];

    const int t = threadIdx.x;
    const int tx = t & 15, ty = t >> 4;
    const int i0 = blockIdx.y * 32, j0 = blockIdx.x * 32;

#pragma unroll
    for (int r = 0; r < 3; r++) {
        int idx = t + r * 256;
        int hp = idx / 6, c = idx - hp * 6;
        WeP[hp * 16 + 2 * c]     = We[(size_t)(2 * hp) * WELD + c];
        WeP[hp * 16 + 2 * c + 1] = We[(size_t)(2 * hp + 1) * WELD + c];
    }

    const int ia0 = i0 + ty, ia1 = i0 + ty + 16;
    const int ja0 = j0 + tx, ja1 = j0 + tx + 16;
    ull e[2][2][6];
#pragma unroll
    for (int a = 0; a < 2; a++)
#pragma unroll
        for (int b = 0; b < 2; b++) {
            int i = a ? ia1 : ia0, j = b ? ja1 : ja0;
            const float* ep = edges + ((size_t)i * Nn + j) * 6;
            float2 x0 = *(const float2*)ep;
            float2 x1 = *(const float2*)(ep + 2);
            float2 x2 = *(const float2*)(ep + 4);
            e[a][b][0] = pack2(x0.x, x0.x); e[a][b][1] = pack2(x0.y, x0.y);
            e[a][b][2] = pack2(x1.x, x1.x); e[a][b][3] = pack2(x1.y, x1.y);
            e[a][b][4] = pack2(x2.x, x2.x); e[a][b][5] = pack2(x2.y, x2.y);
        }

    ull z = pack2(0.f, 0.f);
    ull acc[2][2] = {{z, z}, {z, z}};
    const float* qr0 = qs + ty * PA_STR;
    const float* qr1 = qs + (ty + 16) * PA_STR;
    const float* fr0 = fs + tx * PA_STR;
    const float* fr1 = fs + (tx + 16) * PA_STR;

    for (int half = 0; half < 2; half++) {
        if (half) __syncthreads();
        const int hoff = half * 128;
#pragma unroll
        for (int r = 0; r < 4; r++) {
            int idx = t + r * 256;
            int il = idx >> 5, hq = (idx & 31) << 2;
            float4 a = *(const float4*)(qkm + (size_t)(i0 + il) * HIDD + hoff + hq);
            float4 b = *(const float4*)(Fm  + (size_t)(j0 + il) * HIDD + hoff + hq);
            float* qd = qs + il * PA_STR + hq;
            *(float2*)(qd)     = make_float2(a.x, a.y);
            *(float2*)(qd + 2) = make_float2(a.z, a.w);
            float* fd = fs + il * PA_STR + hq;
            *(float2*)(fd)     = make_float2(b.x, b.y);
            *(float2*)(fd + 2) = make_float2(b.z, b.w);
        }
        __syncthreads();

#pragma unroll 2
        for (int hl = 0; hl < 64; hl++) {
            const ulonglong2* wv =
                (const ulonglong2*)(WeP + (half * 64 + hl) * 16);
            ulonglong2 wA = wv[0], wB = wv[1], wC = wv[2];
            ull q0 = *(const ull*)(qr0 + 2 * hl);
            ull q1 = *(const ull*)(qr1 + 2 * hl);
            ull f0 = *(const ull*)(fr0 + 2 * hl);
            ull f1 = *(const ull*)(fr1 + 2 * hl);
#pragma unroll
            for (int a = 0; a < 2; a++) {
                ull qa = a ? q1 : q0;
#pragma unroll
                for (int b = 0; b < 2; b++) {
                    ull g = b ? f1 : f0;
                    g = fma2(e[a][b][0], wA.x, g);
                    g = fma2(e[a][b][1], wA.y, g);
                    g = fma2(e[a][b][2], wB.x, g);
                    g = fma2(e[a][b][3], wB.y, g);
                    g = fma2(e[a][b][4], wC.x, g);
                    g = fma2(e[a][b][5], wC.y, g);
                    g = relu2(g);
                    acc[a][b] = fma2(qa, g, acc[a][b]);
                }
            }
        }
    }
    {
        float2 v;
        v = unp2(acc[0][0]); S[(size_t)ia0 * Nn + ja0] = v.x + v.y;
        v = unp2(acc[0][1]); S[(size_t)ia0 * Nn + ja1] = v.x + v.y;
        v = unp2(acc[1][0]); S[(size_t)ia1 * Nn + ja0] = v.x + v.y;
        v = unp2(acc[1][1]); S[(size_t)ia1 * Nn + ja1] = v.x + v.y;
    }
}

// ---------------- softmax ----------------
__global__ __launch_bounds__(256) void softmax_k(float* __restrict__ S)
{
    const int i = blockIdx.x, t = threadIdx.x;
    float v0 = S[(size_t)i * Nn + t];
    float v1 = S[(size_t)i * Nn + 256 + t];
    if (t == i)       v0 = -1e30f;
    if (t + 256 == i) v1 = -1e30f;

    __shared__ float red[16];
    float m = fmaxf(v0, v1);
#pragma unroll
    for (int o = 16; o; o >>= 1) m = fmaxf(m, __shfl_xor_sync(0xffffffffu, m, o));
    if ((t & 31) == 0) red[t >> 5] = m;
    __syncthreads();
    m = red[0];
#pragma unroll
    for (int k = 1; k < 8; k++) m = fmaxf(m, red[k]);

    float p0 = __expf(v0 - m), p1 = __expf(v1 - m);
    float s = p0 + p1;
#pragma unroll
    for (int o = 16; o; o >>= 1) s += __shfl_xor_sync(0xffffffffu, s, o);
    if ((t & 31) == 0) red[8 + (t >> 5)] = s;
    __syncthreads();
    s = 0.f;
#pragma unroll
    for (int k = 0; k < 8; k++) s += red[8 + k];
    float inv = 1.f / s;
    S[(size_t)i * Nn + t]       = p0 * inv;
    S[(size_t)i * Nn + 256 + t] = p1 * inv;
}

// ---------------- pass B ----------------
#define PBF_STR 258
#define PBE_STR 200
#define PB_SMEM ((32 * PBF_STR + 32 * PBE_STR + 32 * 16 * 2) * 4)

__global__ __launch_bounds__(256) void passB_k(
    const float* __restrict__ edges,
    const float* __restrict__ We,
    const float* __restrict__ Fm,
    const float* __restrict__ A,
    float* __restrict__ wp)
{
    extern __shared__ __align__(16) float sm[];
    float* Fd  = sm;
    float* EAe = sm + 32 * PBF_STR;
    ull*   Aa  = (ull*)(EAe + 32 * PBE_STR);

    const int t = threadIdx.x;
    const int hp = t & 127, grp = t >> 7;
    const int i0 = blockIdx.y * 32;
    const int j0 = blockIdx.x * 32;

    ull Wr0[6], Wr1[6];
#pragma unroll
    for (int c = 0; c < 6; c++) {
        float w0 = We[(size_t)(2 * hp) * WELD + c];
        float w1 = We[(size_t)(2 * hp + 1) * WELD + c];
        Wr0[c] = pack2(w0, w0);
        Wr1[c] = pack2(w1, w1);
    }

#pragma unroll
    for (int r = 0; r < 8; r++) {
        int idx = t + r * 256;
        int jj = idx >> 6, hq = (idx & 63) << 2;
        float4 b = *(const float4*)(Fm + (size_t)(j0 + jj) * HIDD + hq);
        float* fd = Fd + jj * PBF_STR + hq;
        *(float2*)(fd)     = make_float2(b.x, b.y);
        *(float2*)(fd + 2) = make_float2(b.z, b.w);
    }
#pragma unroll
    for (int r = 0; r < 4; r++) {
        int idx = t + r * 256;
        int ii = idx >> 5, jj = idx & 31;
        int ip = ii >> 1, hf = ii & 1;
        const float* ep = edges + ((size_t)(i0 + ii) * Nn + (j0 + jj)) * 6;
        float2 x0 = *(const float2*)ep;
        float2 x1 = *(const float2*)(ep + 2);
        float2 x2 = *(const float2*)(ep + 4);
        float* d = EAe + jj * PBE_STR + ip * 12;
        d[0 + hf]  = x0.x; d[2 + hf]  = x0.y; d[4 + hf]  = x1.x;
        d[6 + hf]  = x1.y; d[8 + hf]  = x2.x; d[10 + hf] = x2.y;
        ((float*)Aa)[(jj * 16 + ip) * 2 + hf] =
            A[(size_t)(i0 + ii) * Nn + (j0 + jj)];
    }
    __syncthreads();

    ull z = pack2(0.f, 0.f);
    ull acc0[8], acc1[8];
#pragma unroll
    for (int p = 0; p < 8; p++) { acc0[p] = z; acc1[p] = z; }

#pragma unroll 1
    for (int jj = 0; jj < 32; jj++) {
        ull f2 = *(const ull*)(Fd + jj * PBF_STR + 2 * hp);
        float2 fv = unp2(f2);
        ull fr0 = pack2(fv.x, fv.x);
        ull fr1 = pack2(fv.y, fv.y);
        const float* ebase = EAe + jj * PBE_STR + grp * 96;
        const ull*   abase = Aa + jj * 16 + grp * 8;
#pragma unroll
        for (int p = 0; p < 8; p++) {
            const ulonglong2* ev = (const ulonglong2*)(ebase + p * 12);
            ulonglong2 eA = ev[0], eB = ev[1], eC = ev[2];
            ull a2 = abase[p];
            ull g = fma2(eA.x, Wr0[0], fr0);
            g = fma2(eA.y, Wr0[1], g);
            g = fma2(eB.x, Wr0[2], g);
            g = fma2(eB.y, Wr0[3], g);
            g = fma2(eC.x, Wr0[4], g);
            g = fma2(eC.y, Wr0[5], g);
            g = relu2(g);
            acc0[p] = fma2(a2, g, acc0[p]);
            ull h = fma2(eA.x, Wr1[0], fr1);
            h = fma2(eA.y, Wr1[1], h);
            h = fma2(eB.x, Wr1[2], h);
            h = fma2(eB.y, Wr1[3], h);
            h = fma2(eC.x, Wr1[4], h);
            h = fma2(eC.y, Wr1[5], h);
            h = relu2(h);
            acc1[p] = fma2(a2, h, acc1[p]);
        }
    }

    float* dst = wp + (size_t)blockIdx.x * (Nn * HIDD);
#pragma unroll
    for (int p = 0; p < 8; p++) {
        int ie = i0 + (grp * 8 + p) * 2;
        float2 v0 = unp2(acc0[p]);
        float2 v1 = unp2(acc1[p]);
        *(float2*)(dst + (size_t)ie * HIDD + 2 * hp) =
            make_float2(v0.x, v1.x);
        *(float2*)(dst + (size_t)(ie + 1) * HIDD + 2 * hp) =
            make_float2(v0.y, v1.y);
    }
}

// ---------------- reduce 16 partials ----------------
__global__ __launch_bounds__(256) void reduce_w_k(const float* __restrict__ wp,
                                                  float* __restrict__ w)
{
    int i4 = blockIdx.x * 256 + threadIdx.x;
    float4 s = ((const float4*)wp)[i4];
#pragma unroll
    for (int b = 1; b < NPART; b++) {
        float4 v = ((const float4*)(wp + (size_t)b * Nn * HIDD))[i4];
        s.x += v.x; s.y += v.y; s.z += v.z; s.w += v.w;
    }
    ((float4*)w)[i4] = s;
}

// ---------------- launch ----------------
extern "C" void kernel_launch(void* const* d_in, const int* in_sizes, int n_in,
                              void* d_out, int out_size)
{
    const float* app   = (const float*)d_in[0];
    const float* edges = (const float*)d_in[1];
    const float* We    = (const float*)d_in[2];
    const float* be    = (const float*)d_in[3];
    const float* Wq    = (const float*)d_in[4];
    const float* bq    = (const float*)d_in[5];
    const float* Wk    = (const float*)d_in[6];
    // d_in[7] = bk: per-row constant in S -> cancels in softmax
    const float* Wv    = (const float*)d_in[8];
    const float* bv    = (const float*)d_in[9];
    const float* Wo    = (const float*)d_in[10];
    const float* bo    = (const float*)d_in[11];
    float* out = (float*)d_out;

    float *F, *q, *qk, *S, *wp, *w, *agg;
    cudaGetSymbolAddress((void**)&F,   g_F);
    cudaGetSymbolAddress((void**)&q,   g_q);
    cudaGetSymbolAddress((void**)&qk,  g_qk);
    cudaGetSymbolAddress((void**)&S,   g_S);
    cudaGetSymbolAddress((void**)&wp,  g_wp);
    cudaGetSymbolAddress((void**)&w,   g_w);
    cudaGetSymbolAddress((void**)&agg, g_agg);

    cudaFuncSetAttribute(passB_k, cudaFuncAttributeMaxDynamicSharedMemorySize,
                         PB_SMEM);

    gemm_k<true><<<dim3(HIDD / 32, Nn / 32), 256>>>(
        app, IND, We + 6, WELD, be, F, HIDD, IND, 1.f);
    gemm_k<true><<<dim3(AH / 32, Nn / 32), 256>>>(
        app, IND, Wq, IND, bq, q, AH, IND, 1.f);
    gemm_k<false><<<dim3(HIDD / 32, Nn / 32), 256>>>(
        q, AH, Wk, HIDD, nullptr, qk, HIDD, AH, 0.08838834764831845f);

    passA_k<<<dim3(Nn / 32, Nn / 32), 256>>>(edges, We, F, qk, S);
    softmax_k<<<Nn, 256>>>(S);
    passB_k<<<dim3(Nn / 32, Nn / 32), 256, PB_SMEM>>>(edges, We, F, S, wp);
    reduce_w_k<<<Nn * HIDD / 4 / 256, 256>>>(wp, w);

    gemm_k<true><<<dim3(HIDD / 32, Nn / 32), 256>>>(
        w, HIDD, Wv, HIDD, bv, agg, HIDD, HIDD, 1.f);
    gemm_cat2_k<<<dim3(OUTD / 32, Nn / 32), 256>>>(app, agg, Wo, bo, out);
}

// round 5
// speedup vs baseline: 1.1596x; 1.0197x over previous
#include <cuda_runtime.h>
#include <cstddef>

typedef unsigned long long ull;

#define Nn   512
#define IND  256
#define HIDD 256
#define AH   128
#define OUTD 256
#define WELD 262   // IN_DIM + 6
#define NPART 16   // passB j-partials

// ---------------- scratch ----------------
__device__ float g_F[Nn * HIDD];
__device__ float g_q[Nn * AH];
__device__ float g_qk[Nn * HIDD];
__device__ float g_S[Nn * Nn];
__device__ float g_wp[NPART * Nn * HIDD];
__device__ float g_w[Nn * HIDD];
__device__ float g_agg[Nn * HIDD];

// ---------------- f32x2 helpers ----------------
__device__ __forceinline__ ull pack2(float lo, float hi) {
    ull r; asm("mov.b64 %0,{%1,%2};" : "=l"(r) : "f"(lo), "f"(hi)); return r;
}
__device__ __forceinline__ float2 unp2(ull x) {
    float2 f; asm("mov.b64 {%0,%1},%2;" : "=f"(f.x), "=f"(f.y) : "l"(x)); return f;
}
__device__ __forceinline__ ull fma2(ull a, ull b, ull c) {
    ull d; asm("fma.rn.f32x2 %0,%1,%2,%3;" : "=l"(d) : "l"(a), "l"(b), "l"(c)); return d;
}
__device__ __forceinline__ ull relu2(ull x) {
    ull r;
    asm("{.reg .f32 lo,hi;\n\t"
        "mov.b64 {lo,hi},%1;\n\t"
        "max.f32 lo,lo,0f00000000;\n\t"
        "max.f32 hi,hi,0f00000000;\n\t"
        "mov.b64 %0,{lo,hi};}" : "=l"(r) : "l"(x));
    return r;
}

// ---------------- small fp32 GEMM ----------------
template <bool TRANSB>
__global__ __launch_bounds__(256) void gemm_k(
    const float* __restrict__ A, int lda,
    const float* __restrict__ B, int ldb,
    const float* __restrict__ bias,
    float* __restrict__ C, int ldc,
    int K, float alpha)
{
    __shared__ float As[32][34];
    __shared__ float Bs[32][34];
    const int t = threadIdx.x;
    const int tx = t & 15, ty = t >> 4;
    const int mb = blockIdx.y * 32, nb = blockIdx.x * 32;
    float a00 = 0.f, a01 = 0.f, a10 = 0.f, a11 = 0.f;

    for (int k0 = 0; k0 < K; k0 += 32) {
#pragma unroll
        for (int r = 0; r < 4; r++) {
            int idx = t + r * 256;
            int p = idx >> 5, s = idx & 31;
            As[s][p] = A[(size_t)(mb + p) * lda + (k0 + s)];
            if (TRANSB)
                Bs[s][p] = B[(size_t)(nb + p) * ldb + (k0 + s)];
            else
                Bs[p][s] = B[(size_t)(k0 + p) * ldb + (nb + s)];
        }
        __syncthreads();
#pragma unroll
        for (int kk = 0; kk < 32; kk++) {
            float2 av = *(const float2*)&As[kk][ty * 2];
            float2 bv = *(const float2*)&Bs[kk][tx * 2];
            a00 = fmaf(av.x, bv.x, a00);
            a01 = fmaf(av.x, bv.y, a01);
            a10 = fmaf(av.y, bv.x, a10);
            a11 = fmaf(av.y, bv.y, a11);
        }
        __syncthreads();
    }

    int m = mb + ty * 2, n = nb + tx * 2;
    float b0 = bias ? bias[n] : 0.f;
    float b1 = bias ? bias[n + 1] : 0.f;
    C[(size_t)m * ldc + n]           = fmaf(alpha, a00, b0);
    C[(size_t)m * ldc + n + 1]       = fmaf(alpha, a01, b1);
    C[(size_t)(m + 1) * ldc + n]     = fmaf(alpha, a10, b0);
    C[(size_t)(m + 1) * ldc + n + 1] = fmaf(alpha, a11, b1);
}

// ---------------- concat-K output GEMM: C = relu([A1|A2] @ B^T + bias) --------
__global__ __launch_bounds__(256) void gemm_cat2_k(
    const float* __restrict__ A1,
    const float* __restrict__ A2,
    const float* __restrict__ B,
    const float* __restrict__ bias,
    float* __restrict__ C)
{
    __shared__ float As[32][34];
    __shared__ float Bs[32][34];
    const int t = threadIdx.x;
    const int tx = t & 15, ty = t >> 4;
    const int mb = blockIdx.y * 32, nb = blockIdx.x * 32;
    float a00 = 0.f, a01 = 0.f, a10 = 0.f, a11 = 0.f;

    for (int k0 = 0; k0 < 512; k0 += 32) {
        const float* Asrc = (k0 < 256) ? A1 : A2;
        const int koff = (k0 < 256) ? k0 : k0 - 256;
#pragma unroll
        for (int r = 0; r < 4; r++) {
            int idx = t + r * 256;
            int p = idx >> 5, s = idx & 31;
            As[s][p] = Asrc[(size_t)(mb + p) * 256 + koff + s];
            Bs[s][p] = B[(size_t)(nb + p) * 512 + k0 + s];
        }
        __syncthreads();
#pragma unroll
        for (int kk = 0; kk < 32; kk++) {
            float2 av = *(const float2*)&As[kk][ty * 2];
            float2 bv = *(const float2*)&Bs[kk][tx * 2];
            a00 = fmaf(av.x, bv.x, a00);
            a01 = fmaf(av.x, bv.y, a01);
            a10 = fmaf(av.y, bv.x, a10);
            a11 = fmaf(av.y, bv.y, a11);
        }
        __syncthreads();
    }

    int m = mb + ty * 2, n = nb + tx * 2;
    float b0 = bias[n], b1 = bias[n + 1];
    C[(size_t)m * OUTD + n]           = fmaxf(a00 + b0, 0.f);
    C[(size_t)m * OUTD + n + 1]       = fmaxf(a01 + b1, 0.f);
    C[(size_t)(m + 1) * OUTD + n]     = fmaxf(a10 + b0, 0.f);
    C[(size_t)(m + 1) * OUTD + n + 1] = fmaxf(a11 + b1, 0.f);
}

// ---------------- pass A: 16i x 32j tile, 128 threads, grid 512 --------------
#define PA_STR 130
__global__ __launch_bounds__(128) void passA_k(
    const float* __restrict__ edges,
    const float* __restrict__ We,
    const float* __restrict__ Fm,
    const float* __restrict__ qkm,
    float* __restrict__ S)
{
    __shared__ __align__(16) float WeP[2048];
    __shared__ float qs[16 * PA_STR];
    __shared__ float fs[32 * PA_STR];

    const int t = threadIdx.x;
    const int tx = t & 15, ty = t >> 4;          // tx: j, ty: i (0..7)
    const int i0 = blockIdx.y * 16, j0 = blockIdx.x * 32;

#pragma unroll
    for (int r = 0; r < 6; r++) {                // 768 WeP entries
        int idx = t + r * 128;
        int hp = idx / 6, c = idx - hp * 6;
        WeP[hp * 16 + 2 * c]     = We[(size_t)(2 * hp) * WELD + c];
        WeP[hp * 16 + 2 * c + 1] = We[(size_t)(2 * hp + 1) * WELD + c];
    }

    const int ia0 = i0 + ty, ia1 = i0 + ty + 8;
    const int ja0 = j0 + tx, ja1 = j0 + tx + 16;
    ull e[2][2][6];
#pragma unroll
    for (int a = 0; a < 2; a++)
#pragma unroll
        for (int b = 0; b < 2; b++) {
            int i = a ? ia1 : ia0, j = b ? ja1 : ja0;
            const float* ep = edges + ((size_t)i * Nn + j) * 6;
            float2 x0 = *(const float2*)ep;
            float2 x1 = *(const float2*)(ep + 2);
            float2 x2 = *(const float2*)(ep + 4);
            e[a][b][0] = pack2(x0.x, x0.x); e[a][b][1] = pack2(x0.y, x0.y);
            e[a][b][2] = pack2(x1.x, x1.x); e[a][b][3] = pack2(x1.y, x1.y);
            e[a][b][4] = pack2(x2.x, x2.x); e[a][b][5] = pack2(x2.y, x2.y);
        }

    ull z = pack2(0.f, 0.f);
    ull acc[2][2] = {{z, z}, {z, z}};
    const float* qr0 = qs + ty * PA_STR;
    const float* qr1 = qs + (ty + 8) * PA_STR;
    const float* fr0 = fs + tx * PA_STR;
    const float* fr1 = fs + (tx + 16) * PA_STR;

    for (int half = 0; half < 2; half++) {
        if (half) __syncthreads();
        const int hoff = half * 128;
#pragma unroll
        for (int r = 0; r < 4; r++) {            // qk: 16 rows x 128 h
            int idx = t + r * 128;
            int il = idx >> 5, hq = (idx & 31) << 2;
            float4 a = *(const float4*)(qkm + (size_t)(i0 + il) * HIDD + hoff + hq);
            float* qd = qs + il * PA_STR + hq;
            *(float2*)(qd)     = make_float2(a.x, a.y);
            *(float2*)(qd + 2) = make_float2(a.z, a.w);
        }
#pragma unroll
        for (int r = 0; r < 8; r++) {            // F: 32 rows x 128 h
            int idx = t + r * 128;
            int jl = idx >> 5, hq = (idx & 31) << 2;
            float4 b = *(const float4*)(Fm + (size_t)(j0 + jl) * HIDD + hoff + hq);
            float* fd = fs + jl * PA_STR + hq;
            *(float2*)(fd)     = make_float2(b.x, b.y);
            *(float2*)(fd + 2) = make_float2(b.z, b.w);
        }
        __syncthreads();

#pragma unroll 2
        for (int hl = 0; hl < 64; hl++) {
            const ulonglong2* wv =
                (const ulonglong2*)(WeP + (half * 64 + hl) * 16);
            ulonglong2 wA = wv[0], wB = wv[1], wC = wv[2];
            ull q0 = *(const ull*)(qr0 + 2 * hl);
            ull q1 = *(const ull*)(qr1 + 2 * hl);
            ull f0 = *(const ull*)(fr0 + 2 * hl);
            ull f1 = *(const ull*)(fr1 + 2 * hl);
#pragma unroll
            for (int a = 0; a < 2; a++) {
                ull qa = a ? q1 : q0;
#pragma unroll
                for (int b = 0; b < 2; b++) {
                    ull g = b ? f1 : f0;
                    g = fma2(e[a][b][0], wA.x, g);
                    g = fma2(e[a][b][1], wA.y, g);
                    g = fma2(e[a][b][2], wB.x, g);
                    g = fma2(e[a][b][3], wB.y, g);
                    g = fma2(e[a][b][4], wC.x, g);
                    g = fma2(e[a][b][5], wC.y, g);
                    g = relu2(g);
                    acc[a][b] = fma2(qa, g, acc[a][b]);
                }
            }
        }
    }
    {
        float2 v;
        v = unp2(acc[0][0]); S[(size_t)ia0 * Nn + ja0] = v.x + v.y;
        v = unp2(acc[0][1]); S[(size_t)ia0 * Nn + ja1] = v.x + v.y;
        v = unp2(acc[1][0]); S[(size_t)ia1 * Nn + ja0] = v.x + v.y;
        v = unp2(acc[1][1]); S[(size_t)ia1 * Nn + ja1] = v.x + v.y;
    }
}

// ---------------- softmax ----------------
__global__ __launch_bounds__(256) void softmax_k(float* __restrict__ S)
{
    const int i = blockIdx.x, t = threadIdx.x;
    float v0 = S[(size_t)i * Nn + t];
    float v1 = S[(size_t)i * Nn + 256 + t];
    if (t == i)       v0 = -1e30f;
    if (t + 256 == i) v1 = -1e30f;

    __shared__ float red[16];
    float m = fmaxf(v0, v1);
#pragma unroll
    for (int o = 16; o; o >>= 1) m = fmaxf(m, __shfl_xor_sync(0xffffffffu, m, o));
    if ((t & 31) == 0) red[t >> 5] = m;
    __syncthreads();
    m = red[0];
#pragma unroll
    for (int k = 1; k < 8; k++) m = fmaxf(m, red[k]);

    float p0 = __expf(v0 - m), p1 = __expf(v1 - m);
    float s = p0 + p1;
#pragma unroll
    for (int o = 16; o; o >>= 1) s += __shfl_xor_sync(0xffffffffu, s, o);
    if ((t & 31) == 0) red[8 + (t >> 5)] = s;
    __syncthreads();
    s = 0.f;
#pragma unroll
    for (int k = 0; k < 8; k++) s += red[8 + k];
    float inv = 1.f / s;
    S[(size_t)i * Nn + t]       = p0 * inv;
    S[(size_t)i * Nn + 256 + t] = p1 * inv;
}

// ---------------- pass B: 16i x 32j tile, 128 threads, grid 512 ---------------
// Thread owns h-pair (2t, 2t+1) and all 8 i-pairs; f32x2 packed over i-pairs.
#define PBF_STR 258
#define PBE_STR 100   // 8 ip * 12 floats, padded; 400B per jj keeps 16B align
__global__ __launch_bounds__(128) void passB_k(
    const float* __restrict__ edges,
    const float* __restrict__ We,
    const float* __restrict__ Fm,
    const float* __restrict__ A,
    float* __restrict__ wp)
{
    __shared__ __align__(16) float Fd[32 * PBF_STR];
    __shared__ __align__(16) float EAe[32 * PBE_STR];
    __shared__ __align__(16) ull   Aa[32 * 9];

    const int t = threadIdx.x;
    const int hp = t;
    const int i0 = blockIdx.y * 16;
    const int j0 = blockIdx.x * 32;

    ull Wr0[6], Wr1[6];
#pragma unroll
    for (int c = 0; c < 6; c++) {
        float w0 = We[(size_t)(2 * hp) * WELD + c];
        float w1 = We[(size_t)(2 * hp + 1) * WELD + c];
        Wr0[c] = pack2(w0, w0);
        Wr1[c] = pack2(w1, w1);
    }

#pragma unroll
    for (int r = 0; r < 16; r++) {               // F: 32 rows x 256 h
        int idx = t + r * 128;
        int jj = idx >> 6, hq = (idx & 63) << 2;
        float4 b = *(const float4*)(Fm + (size_t)(j0 + jj) * HIDD + hq);
        float* fd = Fd + jj * PBF_STR + hq;
        *(float2*)(fd)     = make_float2(b.x, b.y);
        *(float2*)(fd + 2) = make_float2(b.z, b.w);
    }
#pragma unroll
    for (int r = 0; r < 4; r++) {                // edges + A: 16 ii x 32 jj
        int idx = t + r * 128;
        int ii = idx >> 5, jj = idx & 31;
        int ip = ii >> 1, hf = ii & 1;
        const float* ep = edges + ((size_t)(i0 + ii) * Nn + (j0 + jj)) * 6;
        float2 x0 = *(const float2*)ep;
        float2 x1 = *(const float2*)(ep + 2);
        float2 x2 = *(const float2*)(ep + 4);
        float* d = EAe + jj * PBE_STR + ip * 12;
        d[0 + hf]  = x0.x; d[2 + hf]  = x0.y; d[4 + hf]  = x1.x;
        d[6 + hf]  = x1.y; d[8 + hf]  = x2.x; d[10 + hf] = x2.y;
        ((float*)Aa)[jj * 18 + ip * 2 + hf] =
            A[(size_t)(i0 + ii) * Nn + (j0 + jj)];
    }
    __syncthreads();

    ull z = pack2(0.f, 0.f);
    ull acc0[8], acc1[8];
#pragma unroll
    for (int p = 0; p < 8; p++) { acc0[p] = z; acc1[p] = z; }

#pragma unroll 1
    for (int jj = 0; jj < 32; jj++) {
        ull f2 = *(const ull*)(Fd + jj * PBF_STR + 2 * hp);
        float2 fv = unp2(f2);
        ull fr0 = pack2(fv.x, fv.x);
        ull fr1 = pack2(fv.y, fv.y);
        const float* ebase = EAe + jj * PBE_STR;
        const ull*   abase = Aa + jj * 9;
#pragma unroll
        for (int p = 0; p < 8; p++) {
            const ulonglong2* ev = (const ulonglong2*)(ebase + p * 12);
            ulonglong2 eA = ev[0], eB = ev[1], eC = ev[2];
            ull a2 = abase[p];
            ull g = fma2(eA.x, Wr0[0], fr0);
            g = fma2(eA.y, Wr0[1], g);
            g = fma2(eB.x, Wr0[2], g);
            g = fma2(eB.y, Wr0[3], g);
            g = fma2(eC.x, Wr0[4], g);
            g = fma2(eC.y, Wr0[5], g);
            g = relu2(g);
            acc0[p] = fma2(a2, g, acc0[p]);
            ull h = fma2(eA.x, Wr1[0], fr1);
            h = fma2(eA.y, Wr1[1], h);
            h = fma2(eB.x, Wr1[2], h);
            h = fma2(eB.y, Wr1[3], h);
            h = fma2(eC.x, Wr1[4], h);
            h = fma2(eC.y, Wr1[5], h);
            h = relu2(h);
            acc1[p] = fma2(a2, h, acc1[p]);
        }
    }

    float* dst = wp + (size_t)blockIdx.x * (Nn * HIDD);
#pragma unroll
    for (int p = 0; p < 8; p++) {
        int ie = i0 + p * 2;
        float2 v0 = unp2(acc0[p]);
        float2 v1 = unp2(acc1[p]);
        *(float2*)(dst + (size_t)ie * HIDD + 2 * hp) =
            make_float2(v0.x, v1.x);
        *(float2*)(dst + (size_t)(ie + 1) * HIDD + 2 * hp) =
            make_float2(v0.y, v1.y);
    }
}

// ---------------- reduce 16 partials ----------------
__global__ __launch_bounds__(256) void reduce_w_k(const float* __restrict__ wp,
                                                  float* __restrict__ w)
{
    int i4 = blockIdx.x * 256 + threadIdx.x;
    float4 s = ((const float4*)wp)[i4];
#pragma unroll
    for (int b = 1; b < NPART; b++) {
        float4 v = ((const float4*)(wp + (size_t)b * Nn * HIDD))[i4];
        s.x += v.x; s.y += v.y; s.z += v.z; s.w += v.w;
    }
    ((float4*)w)[i4] = s;
}

// ---------------- launch ----------------
extern "C" void kernel_launch(void* const* d_in, const int* in_sizes, int n_in,
                              void* d_out, int out_size)
{
    const float* app   = (const float*)d_in[0];
    const float* edges = (const float*)d_in[1];
    const float* We    = (const float*)d_in[2];
    const float* be    = (const float*)d_in[3];
    const float* Wq    = (const float*)d_in[4];
    const float* bq    = (const float*)d_in[5];
    const float* Wk    = (const float*)d_in[6];
    // d_in[7] = bk: per-row constant in S -> cancels in softmax
    const float* Wv    = (const float*)d_in[8];
    const float* bv    = (const float*)d_in[9];
    const float* Wo    = (const float*)d_in[10];
    const float* bo    = (const float*)d_in[11];
    float* out = (float*)d_out;

    float *F, *q, *qk, *S, *wp, *w, *agg;
    cudaGetSymbolAddress((void**)&F,   g_F);
    cudaGetSymbolAddress((void**)&q,   g_q);
    cudaGetSymbolAddress((void**)&qk,  g_qk);
    cudaGetSymbolAddress((void**)&S,   g_S);
    cudaGetSymbolAddress((void**)&wp,  g_wp);
    cudaGetSymbolAddress((void**)&w,   g_w);
    cudaGetSymbolAddress((void**)&agg, g_agg);

    gemm_k<true><<<dim3(HIDD / 32, Nn / 32), 256>>>(
        app, IND, We + 6, WELD, be, F, HIDD, IND, 1.f);
    gemm_k<true><<<dim3(AH / 32, Nn / 32), 256>>>(
        app, IND, Wq, IND, bq, q, AH, IND, 1.f);
    gemm_k<false><<<dim3(HIDD / 32, Nn / 32), 256>>>(
        q, AH, Wk, HIDD, nullptr, qk, HIDD, AH, 0.08838834764831845f);

    passA_k<<<dim3(Nn / 32, Nn / 16), 128>>>(edges, We, F, qk, S);
    softmax_k<<<Nn, 256>>>(S);
    passB_k<<<dim3(Nn / 32, Nn / 16), 128>>>(edges, We, F, S, wp);
    reduce_w_k<<<Nn * HIDD / 4 / 256, 256>>>(wp, w);

    gemm_k<true><<<dim3(HIDD / 32, Nn / 32), 256>>>(
        w, HIDD, Wv, HIDD, bv, agg, HIDD, HIDD, 1.f);
    gemm_cat2_k<<<dim3(OUTD / 32, Nn / 32), 256>>>(app, agg, Wo, bo, out);
}

// round 6
// speedup vs baseline: 1.2083x; 1.0420x over previous
#include <cuda_runtime.h>
#include <cstddef>

typedef unsigned long long ull;

#define Nn   512
#define IND  256
#define HIDD 256
#define AH   128
#define OUTD 256
#define WELD 262   // IN_DIM + 6
#define NPART 16   // passB j-partials

// ---------------- scratch ----------------
__device__ float g_F[Nn * HIDD];
__device__ float g_q[Nn * AH];
__device__ float g_qk[Nn * HIDD];
__device__ float g_S[Nn * Nn];
__device__ float g_wp[NPART * Nn * HIDD];
__device__ float g_w[Nn * HIDD];
__device__ float g_agg[Nn * HIDD];

// ---------------- f32x2 helpers ----------------
__device__ __forceinline__ ull pack2(float lo, float hi) {
    ull r; asm("mov.b64 %0,{%1,%2};" : "=l"(r) : "f"(lo), "f"(hi)); return r;
}
__device__ __forceinline__ float2 unp2(ull x) {
    float2 f; asm("mov.b64 {%0,%1},%2;" : "=f"(f.x), "=f"(f.y) : "l"(x)); return f;
}
__device__ __forceinline__ ull fma2(ull a, ull b, ull c) {
    ull d; asm("fma.rn.f32x2 %0,%1,%2,%3;" : "=l"(d) : "l"(a), "l"(b), "l"(c)); return d;
}
__device__ __forceinline__ ull relu2(ull x) {
    ull r;
    asm("{.reg .f32 lo,hi;\n\t"
        "mov.b64 {lo,hi},%1;\n\t"
        "max.f32 lo,lo,0f00000000;\n\t"
        "max.f32 hi,hi,0f00000000;\n\t"
        "mov.b64 %0,{lo,hi};}" : "=l"(r) : "l"(x));
    return r;
}

// ---------------- small fp32 GEMM ----------------
template <bool TRANSB>
__global__ __launch_bounds__(256) void gemm_k(
    const float* __restrict__ A, int lda,
    const float* __restrict__ B, int ldb,
    const float* __restrict__ bias,
    float* __restrict__ C, int ldc,
    int K, float alpha)
{
    __shared__ float As[32][34];
    __shared__ float Bs[32][34];
    const int t = threadIdx.x;
    const int tx = t & 15, ty = t >> 4;
    const int mb = blockIdx.y * 32, nb = blockIdx.x * 32;
    float a00 = 0.f, a01 = 0.f, a10 = 0.f, a11 = 0.f;

    for (int k0 = 0; k0 < K; k0 += 32) {
#pragma unroll
        for (int r = 0; r < 4; r++) {
            int idx = t + r * 256;
            int p = idx >> 5, s = idx & 31;
            As[s][p] = A[(size_t)(mb + p) * lda + (k0 + s)];
            if (TRANSB)
                Bs[s][p] = B[(size_t)(nb + p) * ldb + (k0 + s)];
            else
                Bs[p][s] = B[(size_t)(k0 + p) * ldb + (nb + s)];
        }
        __syncthreads();
#pragma unroll
        for (int kk = 0; kk < 32; kk++) {
            float2 av = *(const float2*)&As[kk][ty * 2];
            float2 bv = *(const float2*)&Bs[kk][tx * 2];
            a00 = fmaf(av.x, bv.x, a00);
            a01 = fmaf(av.x, bv.y, a01);
            a10 = fmaf(av.y, bv.x, a10);
            a11 = fmaf(av.y, bv.y, a11);
        }
        __syncthreads();
    }

    int m = mb + ty * 2, n = nb + tx * 2;
    float b0 = bias ? bias[n] : 0.f;
    float b1 = bias ? bias[n + 1] : 0.f;
    C[(size_t)m * ldc + n]           = fmaf(alpha, a00, b0);
    C[(size_t)m * ldc + n + 1]       = fmaf(alpha, a01, b1);
    C[(size_t)(m + 1) * ldc + n]     = fmaf(alpha, a10, b0);
    C[(size_t)(m + 1) * ldc + n + 1] = fmaf(alpha, a11, b1);
}

// ---------------- fused F + q GEMM (shared A = app) ----------------
// blockIdx.x < 8: F = app @ We[:,6:]^T + be ; else q = app @ Wq^T + bq
__global__ __launch_bounds__(256) void gemm_fq_k(
    const float* __restrict__ app,
    const float* __restrict__ We6,
    const float* __restrict__ Wq,
    const float* __restrict__ be,
    const float* __restrict__ bq,
    float* __restrict__ F,
    float* __restrict__ q)
{
    const bool isF = blockIdx.x < 8;
    const float* B    = isF ? We6 : Wq;
    const int    ldb  = isF ? WELD : IND;
    const float* bias = isF ? be : bq;
    float*       C    = isF ? F : q;
    const int    ldc  = isF ? HIDD : AH;
    const int    nb   = (isF ? blockIdx.x : blockIdx.x - 8) * 32;

    __shared__ float As[32][34];
    __shared__ float Bs[32][34];
    const int t = threadIdx.x;
    const int tx = t & 15, ty = t >> 4;
    const int mb = blockIdx.y * 32;
    float a00 = 0.f, a01 = 0.f, a10 = 0.f, a11 = 0.f;

    for (int k0 = 0; k0 < IND; k0 += 32) {
#pragma unroll
        for (int r = 0; r < 4; r++) {
            int idx = t + r * 256;
            int p = idx >> 5, s = idx & 31;
            As[s][p] = app[(size_t)(mb + p) * IND + (k0 + s)];
            Bs[s][p] = B[(size_t)(nb + p) * ldb + (k0 + s)];
        }
        __syncthreads();
#pragma unroll
        for (int kk = 0; kk < 32; kk++) {
            float2 av = *(const float2*)&As[kk][ty * 2];
            float2 bv = *(const float2*)&Bs[kk][tx * 2];
            a00 = fmaf(av.x, bv.x, a00);
            a01 = fmaf(av.x, bv.y, a01);
            a10 = fmaf(av.y, bv.x, a10);
            a11 = fmaf(av.y, bv.y, a11);
        }
        __syncthreads();
    }

    int m = mb + ty * 2, n = nb + tx * 2;
    C[(size_t)m * ldc + n]           = a00 + bias[n];
    C[(size_t)m * ldc + n + 1]       = a01 + bias[n + 1];
    C[(size_t)(m + 1) * ldc + n]     = a10 + bias[n];
    C[(size_t)(m + 1) * ldc + n + 1] = a11 + bias[n + 1];
}

// ---------------- concat-K output GEMM: C = relu([A1|A2] @ B^T + bias) --------
__global__ __launch_bounds__(256) void gemm_cat2_k(
    const float* __restrict__ A1,
    const float* __restrict__ A2,
    const float* __restrict__ B,
    const float* __restrict__ bias,
    float* __restrict__ C)
{
    __shared__ float As[32][34];
    __shared__ float Bs[32][34];
    const int t = threadIdx.x;
    const int tx = t & 15, ty = t >> 4;
    const int mb = blockIdx.y * 32, nb = blockIdx.x * 32;
    float a00 = 0.f, a01 = 0.f, a10 = 0.f, a11 = 0.f;

    for (int k0 = 0; k0 < 512; k0 += 32) {
        const float* Asrc = (k0 < 256) ? A1 : A2;
        const int koff = (k0 < 256) ? k0 : k0 - 256;
#pragma unroll
        for (int r = 0; r < 4; r++) {
            int idx = t + r * 256;
            int p = idx >> 5, s = idx & 31;
            As[s][p] = Asrc[(size_t)(mb + p) * 256 + koff + s];
            Bs[s][p] = B[(size_t)(nb + p) * 512 + k0 + s];
        }
        __syncthreads();
#pragma unroll
        for (int kk = 0; kk < 32; kk++) {
            float2 av = *(const float2*)&As[kk][ty * 2];
            float2 bv = *(const float2*)&Bs[kk][tx * 2];
            a00 = fmaf(av.x, bv.x, a00);
            a01 = fmaf(av.x, bv.y, a01);
            a10 = fmaf(av.y, bv.x, a10);
            a11 = fmaf(av.y, bv.y, a11);
        }
        __syncthreads();
    }

    int m = mb + ty * 2, n = nb + tx * 2;
    float b0 = bias[n], b1 = bias[n + 1];
    C[(size_t)m * OUTD + n]           = fmaxf(a00 + b0, 0.f);
    C[(size_t)m * OUTD + n + 1]       = fmaxf(a01 + b1, 0.f);
    C[(size_t)(m + 1) * OUTD + n]     = fmaxf(a10 + b0, 0.f);
    C[(size_t)(m + 1) * OUTD + n + 1] = fmaxf(a11 + b1, 0.f);
}

// ---------------- pass A: 16i x 32j tile, 128 threads, prefetch --------------
#define PA_STR 130
__global__ __launch_bounds__(128, 4) void passA_k(
    const float* __restrict__ edges,
    const float* __restrict__ We,
    const float* __restrict__ Fm,
    const float* __restrict__ qkm,
    float* __restrict__ S)
{
    __shared__ __align__(16) float WeP[2048];
    __shared__ float qs[16 * PA_STR];
    __shared__ float fs[32 * PA_STR];

    const int t = threadIdx.x;
    const int tx = t & 15, ty = t >> 4;
    const int i0 = blockIdx.y * 16, j0 = blockIdx.x * 32;

#pragma unroll
    for (int r = 0; r < 6; r++) {
        int idx = t + r * 128;
        int hp = idx / 6, c = idx - hp * 6;
        WeP[hp * 16 + 2 * c]     = We[(size_t)(2 * hp) * WELD + c];
        WeP[hp * 16 + 2 * c + 1] = We[(size_t)(2 * hp + 1) * WELD + c];
    }

    const int ia0 = i0 + ty, ia1 = i0 + ty + 8;
    const int ja0 = j0 + tx, ja1 = j0 + tx + 16;
    ull e[2][2][6];
#pragma unroll
    for (int a = 0; a < 2; a++)
#pragma unroll
        for (int b = 0; b < 2; b++) {
            int i = a ? ia1 : ia0, j = b ? ja1 : ja0;
            const float* ep = edges + ((size_t)i * Nn + j) * 6;
            float2 x0 = *(const float2*)ep;
            float2 x1 = *(const float2*)(ep + 2);
            float2 x2 = *(const float2*)(ep + 4);
            e[a][b][0] = pack2(x0.x, x0.x); e[a][b][1] = pack2(x0.y, x0.y);
            e[a][b][2] = pack2(x1.x, x1.x); e[a][b][3] = pack2(x1.y, x1.y);
            e[a][b][4] = pack2(x2.x, x2.x); e[a][b][5] = pack2(x2.y, x2.y);
        }

    ull z = pack2(0.f, 0.f);
    ull acc[2][2] = {{z, z}, {z, z}};
    const float* qr0 = qs + ty * PA_STR;
    const float* qr1 = qs + (ty + 8) * PA_STR;
    const float* fr0 = fs + tx * PA_STR;
    const float* fr1 = fs + (tx + 16) * PA_STR;

    for (int half = 0; half < 2; half++) {
        if (half) __syncthreads();
        const int hoff = half * 128;
#pragma unroll
        for (int r = 0; r < 4; r++) {
            int idx = t + r * 128;
            int il = idx >> 5, hq = (idx & 31) << 2;
            float4 a = *(const float4*)(qkm + (size_t)(i0 + il) * HIDD + hoff + hq);
            float* qd = qs + il * PA_STR + hq;
            *(float2*)(qd)     = make_float2(a.x, a.y);
            *(float2*)(qd + 2) = make_float2(a.z, a.w);
        }
#pragma unroll
        for (int r = 0; r < 8; r++) {
            int idx = t + r * 128;
            int jl = idx >> 5, hq = (idx & 31) << 2;
            float4 b = *(const float4*)(Fm + (size_t)(j0 + jl) * HIDD + hoff + hq);
            float* fd = fs + jl * PA_STR + hq;
            *(float2*)(fd)     = make_float2(b.x, b.y);
            *(float2*)(fd + 2) = make_float2(b.z, b.w);
        }
        __syncthreads();

        const float* WePh = WeP + half * 1024;
        // prefetch hl = 0
        ulonglong2 wA, wB, wC;
        ull q0, q1, f0, f1;
        {
            const ulonglong2* wv = (const ulonglong2*)WePh;
            wA = wv[0]; wB = wv[1]; wC = wv[2];
            q0 = *(const ull*)(qr0);
            q1 = *(const ull*)(qr1);
            f0 = *(const ull*)(fr0);
            f1 = *(const ull*)(fr1);
        }
#pragma unroll 8
        for (int hl = 0; hl < 64; hl++) {
            ulonglong2 cA = wA, cB = wB, cC = wC;
            ull cq0 = q0, cq1 = q1, cf0 = f0, cf1 = f1;
            if (hl < 63) {   // prefetch next iteration
                const ulonglong2* wv =
                    (const ulonglong2*)(WePh + (hl + 1) * 16);
                wA = wv[0]; wB = wv[1]; wC = wv[2];
                q0 = *(const ull*)(qr0 + 2 * (hl + 1));
                q1 = *(const ull*)(qr1 + 2 * (hl + 1));
                f0 = *(const ull*)(fr0 + 2 * (hl + 1));
                f1 = *(const ull*)(fr1 + 2 * (hl + 1));
            }
#pragma unroll
            for (int a = 0; a < 2; a++) {
                ull qa = a ? cq1 : cq0;
#pragma unroll
                for (int b = 0; b < 2; b++) {
                    ull g = b ? cf1 : cf0;
                    g = fma2(e[a][b][0], cA.x, g);
                    g = fma2(e[a][b][1], cA.y, g);
                    g = fma2(e[a][b][2], cB.x, g);
                    g = fma2(e[a][b][3], cB.y, g);
                    g = fma2(e[a][b][4], cC.x, g);
                    g = fma2(e[a][b][5], cC.y, g);
                    g = relu2(g);
                    acc[a][b] = fma2(qa, g, acc[a][b]);
                }
            }
        }
    }
    {
        float2 v;
        v = unp2(acc[0][0]); S[(size_t)ia0 * Nn + ja0] = v.x + v.y;
        v = unp2(acc[0][1]); S[(size_t)ia0 * Nn + ja1] = v.x + v.y;
        v = unp2(acc[1][0]); S[(size_t)ia1 * Nn + ja0] = v.x + v.y;
        v = unp2(acc[1][1]); S[(size_t)ia1 * Nn + ja1] = v.x + v.y;
    }
}

// ---------------- softmax ----------------
__global__ __launch_bounds__(256) void softmax_k(float* __restrict__ S)
{
    const int i = blockIdx.x, t = threadIdx.x;
    float v0 = S[(size_t)i * Nn + t];
    float v1 = S[(size_t)i * Nn + 256 + t];
    if (t == i)       v0 = -1e30f;
    if (t + 256 == i) v1 = -1e30f;

    __shared__ float red[16];
    float m = fmaxf(v0, v1);
#pragma unroll
    for (int o = 16; o; o >>= 1) m = fmaxf(m, __shfl_xor_sync(0xffffffffu, m, o));
    if ((t & 31) == 0) red[t >> 5] = m;
    __syncthreads();
    m = red[0];
#pragma unroll
    for (int k = 1; k < 8; k++) m = fmaxf(m, red[k]);

    float p0 = __expf(v0 - m), p1 = __expf(v1 - m);
    float s = p0 + p1;
#pragma unroll
    for (int o = 16; o; o >>= 1) s += __shfl_xor_sync(0xffffffffu, s, o);
    if ((t & 31) == 0) red[8 + (t >> 5)] = s;
    __syncthreads();
    s = 0.f;
#pragma unroll
    for (int k = 0; k < 8; k++) s += red[8 + k];
    float inv = 1.f / s;
    S[(size_t)i * Nn + t]       = p0 * inv;
    S[(size_t)i * Nn + 256 + t] = p1 * inv;
}

// ---------------- pass B: 16i x 32j tile, 128 threads, prefetch ---------------
#define PBF_STR 258
#define PBE_STR 100
__global__ __launch_bounds__(128, 4) void passB_k(
    const float* __restrict__ edges,
    const float* __restrict__ We,
    const float* __restrict__ Fm,
    const float* __restrict__ A,
    float* __restrict__ wp)
{
    __shared__ __align__(16) float Fd[32 * PBF_STR];
    __shared__ __align__(16) float EAe[32 * PBE_STR];
    __shared__ __align__(16) ull   Aa[32 * 9];

    const int t = threadIdx.x;
    const int hp = t;
    const int i0 = blockIdx.y * 16;
    const int j0 = blockIdx.x * 32;

    ull Wr0[6], Wr1[6];
#pragma unroll
    for (int c = 0; c < 6; c++) {
        float w0 = We[(size_t)(2 * hp) * WELD + c];
        float w1 = We[(size_t)(2 * hp + 1) * WELD + c];
        Wr0[c] = pack2(w0, w0);
        Wr1[c] = pack2(w1, w1);
    }

#pragma unroll
    for (int r = 0; r < 16; r++) {
        int idx = t + r * 128;
        int jj = idx >> 6, hq = (idx & 63) << 2;
        float4 b = *(const float4*)(Fm + (size_t)(j0 + jj) * HIDD + hq);
        float* fd = Fd + jj * PBF_STR + hq;
        *(float2*)(fd)     = make_float2(b.x, b.y);
        *(float2*)(fd + 2) = make_float2(b.z, b.w);
    }
#pragma unroll
    for (int r = 0; r < 4; r++) {
        int idx = t + r * 128;
        int ii = idx >> 5, jj = idx & 31;
        int ip = ii >> 1, hf = ii & 1;
        const float* ep = edges + ((size_t)(i0 + ii) * Nn + (j0 + jj)) * 6;
        float2 x0 = *(const float2*)ep;
        float2 x1 = *(const float2*)(ep + 2);
        float2 x2 = *(const float2*)(ep + 4);
        float* d = EAe + jj * PBE_STR + ip * 12;
        d[0 + hf]  = x0.x; d[2 + hf]  = x0.y; d[4 + hf]  = x1.x;
        d[6 + hf]  = x1.y; d[8 + hf]  = x2.x; d[10 + hf] = x2.y;
        ((float*)Aa)[jj * 18 + ip * 2 + hf] =
            A[(size_t)(i0 + ii) * Nn + (j0 + jj)];
    }
    __syncthreads();

    ull z = pack2(0.f, 0.f);
    ull acc0[8], acc1[8];
#pragma unroll
    for (int p = 0; p < 8; p++) { acc0[p] = z; acc1[p] = z; }

    ull f2n = *(const ull*)(Fd + 2 * hp);   // prefetch jj = 0
#pragma unroll 2
    for (int jj = 0; jj < 32; jj++) {
        ull f2 = f2n;
        if (jj < 31)
            f2n = *(const ull*)(Fd + (jj + 1) * PBF_STR + 2 * hp);
        float2 fv = unp2(f2);
        ull fr0 = pack2(fv.x, fv.x);
        ull fr1 = pack2(fv.y, fv.y);
        const float* ebase = EAe + jj * PBE_STR;
        const ull*   abase = Aa + jj * 9;
#pragma unroll
        for (int p = 0; p < 8; p++) {
            const ulonglong2* ev = (const ulonglong2*)(ebase + p * 12);
            ulonglong2 eA = ev[0], eB = ev[1], eC = ev[2];
            ull a2 = abase[p];
            ull g = fma2(eA.x, Wr0[0], fr0);
            g = fma2(eA.y, Wr0[1], g);
            g = fma2(eB.x, Wr0[2], g);
            g = fma2(eB.y, Wr0[3], g);
            g = fma2(eC.x, Wr0[4], g);
            g = fma2(eC.y, Wr0[5], g);
            g = relu2(g);
            acc0[p] = fma2(a2, g, acc0[p]);
            ull h = fma2(eA.x, Wr1[0], fr1);
            h = fma2(eA.y, Wr1[1], h);
            h = fma2(eB.x, Wr1[2], h);
            h = fma2(eB.y, Wr1[3], h);
            h = fma2(eC.x, Wr1[4], h);
            h = fma2(eC.y, Wr1[5], h);
            h = relu2(h);
            acc1[p] = fma2(a2, h, acc1[p]);
        }
    }

    float* dst = wp + (size_t)blockIdx.x * (Nn * HIDD);
#pragma unroll
    for (int p = 0; p < 8; p++) {
        int ie = i0 + p * 2;
        float2 v0 = unp2(acc0[p]);
        float2 v1 = unp2(acc1[p]);
        *(float2*)(dst + (size_t)ie * HIDD + 2 * hp) =
            make_float2(v0.x, v1.x);
        *(float2*)(dst + (size_t)(ie + 1) * HIDD + 2 * hp) =
            make_float2(v0.y, v1.y);
    }
}

// ---------------- reduce 16 partials ----------------
__global__ __launch_bounds__(256) void reduce_w_k(const float* __restrict__ wp,
                                                  float* __restrict__ w)
{
    int i4 = blockIdx.x * 256 + threadIdx.x;
    float4 s = ((const float4*)wp)[i4];
#pragma unroll
    for (int b = 1; b < NPART; b++) {
        float4 v = ((const float4*)(wp + (size_t)b * Nn * HIDD))[i4];
        s.x += v.x; s.y += v.y; s.z += v.z; s.w += v.w;
    }
    ((float4*)w)[i4] = s;
}

// ---------------- launch ----------------
extern "C" void kernel_launch(void* const* d_in, const int* in_sizes, int n_in,
                              void* d_out, int out_size)
{
    const float* app   = (const float*)d_in[0];
    const float* edges = (const float*)d_in[1];
    const float* We    = (const float*)d_in[2];
    const float* be    = (const float*)d_in[3];
    const float* Wq    = (const float*)d_in[4];
    const float* bq    = (const float*)d_in[5];
    const float* Wk    = (const float*)d_in[6];
    // d_in[7] = bk: per-row constant in S -> cancels in softmax
    const float* Wv    = (const float*)d_in[8];
    const float* bv    = (const float*)d_in[9];
    const float* Wo    = (const float*)d_in[10];
    const float* bo    = (const float*)d_in[11];
    float* out = (float*)d_out;

    float *F, *q, *qk, *S, *wp, *w, *agg;
    cudaGetSymbolAddress((void**)&F,   g_F);
    cudaGetSymbolAddress((void**)&q,   g_q);
    cudaGetSymbolAddress((void**)&qk,  g_qk);
    cudaGetSymbolAddress((void**)&S,   g_S);
    cudaGetSymbolAddress((void**)&wp,  g_wp);
    cudaGetSymbolAddress((void**)&w,   g_w);
    cudaGetSymbolAddress((void**)&agg, g_agg);

    // F and q in one launch (shared A)
    gemm_fq_k<<<dim3(12, Nn / 32), 256>>>(app, We + 6, Wq, be, bq, F, q);
    // qk = (q @ Wk) / sqrt(128)
    gemm_k<false><<<dim3(HIDD / 32, Nn / 32), 256>>>(
        q, AH, Wk, HIDD, nullptr, qk, HIDD, AH, 0.08838834764831845f);

    passA_k<<<dim3(Nn / 32, Nn / 16), 128>>>(edges, We, F, qk, S);
    softmax_k<<<Nn, 256>>>(S);
    passB_k<<<dim3(Nn / 32, Nn / 16), 128>>>(edges, We, F, S, wp);
    reduce_w_k<<<Nn * HIDD / 4 / 256, 256>>>(wp, w);

    gemm_k<true><<<dim3(HIDD / 32, Nn / 32), 256>>>(
        w, HIDD, Wv, HIDD, bv, agg, HIDD, HIDD, 1.f);
    gemm_cat2_k<<<dim3(OUTD / 32, Nn / 32), 256>>>(app, agg, Wo, bo, out);
}

// round 7
// speedup vs baseline: 1.2608x; 1.0435x over previous
#include <cuda_runtime.h>
#include <cstddef>

typedef unsigned long long ull;

#define Nn   512
#define IND  256
#define HIDD 256
#define AH   128
#define OUTD 256
#define WELD 262   // IN_DIM + 6
#define NPART 16   // passB j-partials

// ---------------- scratch ----------------
__device__ float g_F[Nn * HIDD];
__device__ float g_q[Nn * AH];
__device__ float g_qk[Nn * HIDD];
__device__ float g_S[Nn * Nn];
__device__ float g_S2[Nn * Nn];
__device__ float g_wp[NPART * Nn * HIDD];
__device__ float g_w[Nn * HIDD];
__device__ float g_agg[Nn * HIDD];

// ---------------- f32x2 helpers ----------------
__device__ __forceinline__ ull pack2(float lo, float hi) {
    ull r; asm("mov.b64 %0,{%1,%2};" : "=l"(r) : "f"(lo), "f"(hi)); return r;
}
__device__ __forceinline__ float2 unp2(ull x) {
    float2 f; asm("mov.b64 {%0,%1},%2;" : "=f"(f.x), "=f"(f.y) : "l"(x)); return f;
}
__device__ __forceinline__ ull fma2(ull a, ull b, ull c) {
    ull d; asm("fma.rn.f32x2 %0,%1,%2,%3;" : "=l"(d) : "l"(a), "l"(b), "l"(c)); return d;
}
__device__ __forceinline__ ull relu2(ull x) {
    ull r;
    asm("{.reg .f32 lo,hi;\n\t"
        "mov.b64 {lo,hi},%1;\n\t"
        "max.f32 lo,lo,0f00000000;\n\t"
        "max.f32 hi,hi,0f00000000;\n\t"
        "mov.b64 %0,{lo,hi};}" : "=l"(r) : "l"(x));
    return r;
}

// ---------------- small fp32 GEMM ----------------
template <bool TRANSB>
__global__ __launch_bounds__(256) void gemm_k(
    const float* __restrict__ A, int lda,
    const float* __restrict__ B, int ldb,
    const float* __restrict__ bias,
    float* __restrict__ C, int ldc,
    int K, float alpha)
{
    __shared__ float As[32][34];
    __shared__ float Bs[32][34];
    const int t = threadIdx.x;
    const int tx = t & 15, ty = t >> 4;
    const int mb = blockIdx.y * 32, nb = blockIdx.x * 32;
    float a00 = 0.f, a01 = 0.f, a10 = 0.f, a11 = 0.f;

    for (int k0 = 0; k0 < K; k0 += 32) {
#pragma unroll
        for (int r = 0; r < 4; r++) {
            int idx = t + r * 256;
            int p = idx >> 5, s = idx & 31;
            As[s][p] = A[(size_t)(mb + p) * lda + (k0 + s)];
            if (TRANSB)
                Bs[s][p] = B[(size_t)(nb + p) * ldb + (k0 + s)];
            else
                Bs[p][s] = B[(size_t)(k0 + p) * ldb + (nb + s)];
        }
        __syncthreads();
#pragma unroll
        for (int kk = 0; kk < 32; kk++) {
            float2 av = *(const float2*)&As[kk][ty * 2];
            float2 bv = *(const float2*)&Bs[kk][tx * 2];
            a00 = fmaf(av.x, bv.x, a00);
            a01 = fmaf(av.x, bv.y, a01);
            a10 = fmaf(av.y, bv.x, a10);
            a11 = fmaf(av.y, bv.y, a11);
        }
        __syncthreads();
    }

    int m = mb + ty * 2, n = nb + tx * 2;
    float b0 = bias ? bias[n] : 0.f;
    float b1 = bias ? bias[n + 1] : 0.f;
    C[(size_t)m * ldc + n]           = fmaf(alpha, a00, b0);
    C[(size_t)m * ldc + n + 1]       = fmaf(alpha, a01, b1);
    C[(size_t)(m + 1) * ldc + n]     = fmaf(alpha, a10, b0);
    C[(size_t)(m + 1) * ldc + n + 1] = fmaf(alpha, a11, b1);
}

// ---------------- fused F + q GEMM (shared A = app) ----------------
__global__ __launch_bounds__(256) void gemm_fq_k(
    const float* __restrict__ app,
    const float* __restrict__ We6,
    const float* __restrict__ Wq,
    const float* __restrict__ be,
    const float* __restrict__ bq,
    float* __restrict__ F,
    float* __restrict__ q)
{
    const bool isF = blockIdx.x < 8;
    const float* B    = isF ? We6 : Wq;
    const int    ldb  = isF ? WELD : IND;
    const float* bias = isF ? be : bq;
    float*       C    = isF ? F : q;
    const int    ldc  = isF ? HIDD : AH;
    const int    nb   = (isF ? blockIdx.x : blockIdx.x - 8) * 32;

    __shared__ float As[32][34];
    __shared__ float Bs[32][34];
    const int t = threadIdx.x;
    const int tx = t & 15, ty = t >> 4;
    const int mb = blockIdx.y * 32;
    float a00 = 0.f, a01 = 0.f, a10 = 0.f, a11 = 0.f;

    for (int k0 = 0; k0 < IND; k0 += 32) {
#pragma unroll
        for (int r = 0; r < 4; r++) {
            int idx = t + r * 256;
            int p = idx >> 5, s = idx & 31;
            As[s][p] = app[(size_t)(mb + p) * IND + (k0 + s)];
            Bs[s][p] = B[(size_t)(nb + p) * ldb + (k0 + s)];
        }
        __syncthreads();
#pragma unroll
        for (int kk = 0; kk < 32; kk++) {
            float2 av = *(const float2*)&As[kk][ty * 2];
            float2 bv = *(const float2*)&Bs[kk][tx * 2];
            a00 = fmaf(av.x, bv.x, a00);
            a01 = fmaf(av.x, bv.y, a01);
            a10 = fmaf(av.y, bv.x, a10);
            a11 = fmaf(av.y, bv.y, a11);
        }
        __syncthreads();
    }

    int m = mb + ty * 2, n = nb + tx * 2;
    C[(size_t)m * ldc + n]           = a00 + bias[n];
    C[(size_t)m * ldc + n + 1]       = a01 + bias[n + 1];
    C[(size_t)(m + 1) * ldc + n]     = a10 + bias[n];
    C[(size_t)(m + 1) * ldc + n + 1] = a11 + bias[n + 1];
}

// ---------------- concat-K output GEMM: C = relu([A1|A2] @ B^T + bias) --------
__global__ __launch_bounds__(256) void gemm_cat2_k(
    const float* __restrict__ A1,
    const float* __restrict__ A2,
    const float* __restrict__ B,
    const float* __restrict__ bias,
    float* __restrict__ C)
{
    __shared__ float As[32][34];
    __shared__ float Bs[32][34];
    const int t = threadIdx.x;
    const int tx = t & 15, ty = t >> 4;
    const int mb = blockIdx.y * 32, nb = blockIdx.x * 32;
    float a00 = 0.f, a01 = 0.f, a10 = 0.f, a11 = 0.f;

    for (int k0 = 0; k0 < 512; k0 += 32) {
        const float* Asrc = (k0 < 256) ? A1 : A2;
        const int koff = (k0 < 256) ? k0 : k0 - 256;
#pragma unroll
        for (int r = 0; r < 4; r++) {
            int idx = t + r * 256;
            int p = idx >> 5, s = idx & 31;
            As[s][p] = Asrc[(size_t)(mb + p) * 256 + koff + s];
            Bs[s][p] = B[(size_t)(nb + p) * 512 + k0 + s];
        }
        __syncthreads();
#pragma unroll
        for (int kk = 0; kk < 32; kk++) {
            float2 av = *(const float2*)&As[kk][ty * 2];
            float2 bv = *(const float2*)&Bs[kk][tx * 2];
            a00 = fmaf(av.x, bv.x, a00);
            a01 = fmaf(av.x, bv.y, a01);
            a10 = fmaf(av.y, bv.x, a10);
            a11 = fmaf(av.y, bv.y, a11);
        }
        __syncthreads();
    }

    int m = mb + ty * 2, n = nb + tx * 2;
    float b0 = bias[n], b1 = bias[n + 1];
    C[(size_t)m * OUTD + n]           = fmaxf(a00 + b0, 0.f);
    C[(size_t)m * OUTD + n + 1]       = fmaxf(a01 + b1, 0.f);
    C[(size_t)(m + 1) * OUTD + n]     = fmaxf(a10 + b0, 0.f);
    C[(size_t)(m + 1) * OUTD + n + 1] = fmaxf(a11 + b1, 0.f);
}

// ---------------- pass A: 16i x 32j x 128h per block (z = h-half) -------------
// Partial scores into S (z=0) / S2 (z=1); softmax sums them.
#define PA_STR 130
__global__ __launch_bounds__(128, 5) void passA_k(
    const float* __restrict__ edges,
    const float* __restrict__ We,
    const float* __restrict__ Fm,
    const float* __restrict__ qkm,
    float* __restrict__ S0,
    float* __restrict__ S1)
{
    __shared__ __align__(16) float WeP[1024];    // 64 local h-pairs x 16
    __shared__ float qs[16 * PA_STR];
    __shared__ float fs[32 * PA_STR];

    const int t = threadIdx.x;
    const int tx = t & 15, ty = t >> 4;
    const int i0 = blockIdx.y * 16, j0 = blockIdx.x * 32;
    const int hoff = blockIdx.z * 128;

#pragma unroll
    for (int r = 0; r < 3; r++) {                // 384 = 64 pairs x 6 cols
        int idx = t + r * 128;
        int hp = idx / 6, c = idx - hp * 6;
        int gh = hoff + 2 * hp;
        WeP[hp * 16 + 2 * c]     = We[(size_t)gh * WELD + c];
        WeP[hp * 16 + 2 * c + 1] = We[(size_t)(gh + 1) * WELD + c];
    }
#pragma unroll
    for (int r = 0; r < 4; r++) {                // qk: 16 rows x 128 h
        int idx = t + r * 128;
        int il = idx >> 5, hq = (idx & 31) << 2;
        float4 a = *(const float4*)(qkm + (size_t)(i0 + il) * HIDD + hoff + hq);
        float* qd = qs + il * PA_STR + hq;
        *(float2*)(qd)     = make_float2(a.x, a.y);
        *(float2*)(qd + 2) = make_float2(a.z, a.w);
    }
#pragma unroll
    for (int r = 0; r < 8; r++) {                // F: 32 rows x 128 h
        int idx = t + r * 128;
        int jl = idx >> 5, hq = (idx & 31) << 2;
        float4 b = *(const float4*)(Fm + (size_t)(j0 + jl) * HIDD + hoff + hq);
        float* fd = fs + jl * PA_STR + hq;
        *(float2*)(fd)     = make_float2(b.x, b.y);
        *(float2*)(fd + 2) = make_float2(b.z, b.w);
    }

    const int ia0 = i0 + ty, ia1 = i0 + ty + 8;
    const int ja0 = j0 + tx, ja1 = j0 + tx + 16;
    ull e[2][2][6];
#pragma unroll
    for (int a = 0; a < 2; a++)
#pragma unroll
        for (int b = 0; b < 2; b++) {
            int i = a ? ia1 : ia0, j = b ? ja1 : ja0;
            const float* ep = edges + ((size_t)i * Nn + j) * 6;
            float2 x0 = *(const float2*)ep;
            float2 x1 = *(const float2*)(ep + 2);
            float2 x2 = *(const float2*)(ep + 4);
            e[a][b][0] = pack2(x0.x, x0.x); e[a][b][1] = pack2(x0.y, x0.y);
            e[a][b][2] = pack2(x1.x, x1.x); e[a][b][3] = pack2(x1.y, x1.y);
            e[a][b][4] = pack2(x2.x, x2.x); e[a][b][5] = pack2(x2.y, x2.y);
        }
    __syncthreads();

    ull z = pack2(0.f, 0.f);
    ull acc[2][2] = {{z, z}, {z, z}};
    const float* qr0 = qs + ty * PA_STR;
    const float* qr1 = qs + (ty + 8) * PA_STR;
    const float* fr0 = fs + tx * PA_STR;
    const float* fr1 = fs + (tx + 16) * PA_STR;

    // prefetch hl = 0
    ulonglong2 wA, wB, wC;
    ull q0, q1, f0, f1;
    {
        const ulonglong2* wv = (const ulonglong2*)WeP;
        wA = wv[0]; wB = wv[1]; wC = wv[2];
        q0 = *(const ull*)(qr0);
        q1 = *(const ull*)(qr1);
        f0 = *(const ull*)(fr0);
        f1 = *(const ull*)(fr1);
    }
#pragma unroll 8
    for (int hl = 0; hl < 64; hl++) {
        ulonglong2 cA = wA, cB = wB, cC = wC;
        ull cq0 = q0, cq1 = q1, cf0 = f0, cf1 = f1;
        if (hl < 63) {
            const ulonglong2* wv = (const ulonglong2*)(WeP + (hl + 1) * 16);
            wA = wv[0]; wB = wv[1]; wC = wv[2];
            q0 = *(const ull*)(qr0 + 2 * (hl + 1));
            q1 = *(const ull*)(qr1 + 2 * (hl + 1));
            f0 = *(const ull*)(fr0 + 2 * (hl + 1));
            f1 = *(const ull*)(fr1 + 2 * (hl + 1));
        }
#pragma unroll
        for (int a = 0; a < 2; a++) {
            ull qa = a ? cq1 : cq0;
#pragma unroll
            for (int b = 0; b < 2; b++) {
                ull g = b ? cf1 : cf0;
                g = fma2(e[a][b][0], cA.x, g);
                g = fma2(e[a][b][1], cA.y, g);
                g = fma2(e[a][b][2], cB.x, g);
                g = fma2(e[a][b][3], cB.y, g);
                g = fma2(e[a][b][4], cC.x, g);
                g = fma2(e[a][b][5], cC.y, g);
                g = relu2(g);
                acc[a][b] = fma2(qa, g, acc[a][b]);
            }
        }
    }
    {
        float* Sp = blockIdx.z ? S1 : S0;
        float2 v;
        v = unp2(acc[0][0]); Sp[(size_t)ia0 * Nn + ja0] = v.x + v.y;
        v = unp2(acc[0][1]); Sp[(size_t)ia0 * Nn + ja1] = v.x + v.y;
        v = unp2(acc[1][0]); Sp[(size_t)ia1 * Nn + ja0] = v.x + v.y;
        v = unp2(acc[1][1]); Sp[(size_t)ia1 * Nn + ja1] = v.x + v.y;
    }
}

// ---------------- softmax (sums the two h-half partials) ----------------
__global__ __launch_bounds__(256) void softmax_k(float* __restrict__ S,
                                                 const float* __restrict__ S2)
{
    const int i = blockIdx.x, t = threadIdx.x;
    float v0 = S[(size_t)i * Nn + t]       + S2[(size_t)i * Nn + t];
    float v1 = S[(size_t)i * Nn + 256 + t] + S2[(size_t)i * Nn + 256 + t];
    if (t == i)       v0 = -1e30f;
    if (t + 256 == i) v1 = -1e30f;

    __shared__ float red[16];
    float m = fmaxf(v0, v1);
#pragma unroll
    for (int o = 16; o; o >>= 1) m = fmaxf(m, __shfl_xor_sync(0xffffffffu, m, o));
    if ((t & 31) == 0) red[t >> 5] = m;
    __syncthreads();
    m = red[0];
#pragma unroll
    for (int k = 1; k < 8; k++) m = fmaxf(m, red[k]);

    float p0 = __expf(v0 - m), p1 = __expf(v1 - m);
    float s = p0 + p1;
#pragma unroll
    for (int o = 16; o; o >>= 1) s += __shfl_xor_sync(0xffffffffu, s, o);
    if ((t & 31) == 0) red[8 + (t >> 5)] = s;
    __syncthreads();
    s = 0.f;
#pragma unroll
    for (int k = 0; k < 8; k++) s += red[8 + k];
    float inv = 1.f / s;
    S[(size_t)i * Nn + t]       = p0 * inv;
    S[(size_t)i * Nn + 256 + t] = p1 * inv;
}

// ---------------- pass B: 8i x 32j tile, 128 threads, grid (16,64) ------------
// Thread owns h-pair (2t, 2t+1) and 4 i-pairs; f32x2 packed over i-pairs.
#define PBF_STR 258
#define PBE_STR 52
__global__ __launch_bounds__(128, 5) void passB_k(
    const float* __restrict__ edges,
    const float* __restrict__ We,
    const float* __restrict__ Fm,
    const float* __restrict__ A,
    float* __restrict__ wp)
{
    __shared__ __align__(16) float Fd[32 * PBF_STR];
    __shared__ __align__(16) float EAe[32 * PBE_STR];
    __shared__ __align__(16) ull   Aa[32 * 5];

    const int t = threadIdx.x;
    const int hp = t;
    const int i0 = blockIdx.y * 8;
    const int j0 = blockIdx.x * 32;

    ull Wr0[6], Wr1[6];
#pragma unroll
    for (int c = 0; c < 6; c++) {
        float w0 = We[(size_t)(2 * hp) * WELD + c];
        float w1 = We[(size_t)(2 * hp + 1) * WELD + c];
        Wr0[c] = pack2(w0, w0);
        Wr1[c] = pack2(w1, w1);
    }

#pragma unroll
    for (int r = 0; r < 16; r++) {               // F: 32 rows x 256 h
        int idx = t + r * 128;
        int jj = idx >> 6, hq = (idx & 63) << 2;
        float4 b = *(const float4*)(Fm + (size_t)(j0 + jj) * HIDD + hq);
        float* fd = Fd + jj * PBF_STR + hq;
        *(float2*)(fd)     = make_float2(b.x, b.y);
        *(float2*)(fd + 2) = make_float2(b.z, b.w);
    }
#pragma unroll
    for (int r = 0; r < 2; r++) {                // edges + A: 8 ii x 32 jj
        int idx = t + r * 128;
        int ii = idx >> 5, jj = idx & 31;
        int ip = ii >> 1, hf = ii & 1;
        const float* ep = edges + ((size_t)(i0 + ii) * Nn + (j0 + jj)) * 6;
        float2 x0 = *(const float2*)ep;
        float2 x1 = *(const float2*)(ep + 2);
        float2 x2 = *(const float2*)(ep + 4);
        float* d = EAe + jj * PBE_STR + ip * 12;
        d[0 + hf]  = x0.x; d[2 + hf]  = x0.y; d[4 + hf]  = x1.x;
        d[6 + hf]  = x1.y; d[8 + hf]  = x2.x; d[10 + hf] = x2.y;
        ((float*)Aa)[jj * 10 + ip * 2 + hf] =
            A[(size_t)(i0 + ii) * Nn + (j0 + jj)];
    }
    __syncthreads();

    ull z = pack2(0.f, 0.f);
    ull acc0[4], acc1[4];
#pragma unroll
    for (int p = 0; p < 4; p++) { acc0[p] = z; acc1[p] = z; }

    ull f2n = *(const ull*)(Fd + 2 * hp);        // prefetch jj = 0
#pragma unroll 4
    for (int jj = 0; jj < 32; jj++) {
        ull f2 = f2n;
        if (jj < 31)
            f2n = *(const ull*)(Fd + (jj + 1) * PBF_STR + 2 * hp);
        float2 fv = unp2(f2);
        ull fr0 = pack2(fv.x, fv.x);
        ull fr1 = pack2(fv.y, fv.y);
        const float* ebase = EAe + jj * PBE_STR;
        const ull*   abase = Aa + jj * 5;
#pragma unroll
        for (int p = 0; p < 4; p++) {
            const ulonglong2* ev = (const ulonglong2*)(ebase + p * 12);
            ulonglong2 eA = ev[0], eB = ev[1], eC = ev[2];
            ull a2 = abase[p];
            ull g = fma2(eA.x, Wr0[0], fr0);
            g = fma2(eA.y, Wr0[1], g);
            g = fma2(eB.x, Wr0[2], g);
            g = fma2(eB.y, Wr0[3], g);
            g = fma2(eC.x, Wr0[4], g);
            g = fma2(eC.y, Wr0[5], g);
            g = relu2(g);
            acc0[p] = fma2(a2, g, acc0[p]);
            ull h = fma2(eA.x, Wr1[0], fr1);
            h = fma2(eA.y, Wr1[1], h);
            h = fma2(eB.x, Wr1[2], h);
            h = fma2(eB.y, Wr1[3], h);
            h = fma2(eC.x, Wr1[4], h);
            h = fma2(eC.y, Wr1[5], h);
            h = relu2(h);
            acc1[p] = fma2(a2, h, acc1[p]);
        }
    }

    float* dst = wp + (size_t)blockIdx.x * (Nn * HIDD);
#pragma unroll
    for (int p = 0; p < 4; p++) {
        int ie = i0 + p * 2;
        float2 v0 = unp2(acc0[p]);
        float2 v1 = unp2(acc1[p]);
        *(float2*)(dst + (size_t)ie * HIDD + 2 * hp) =
            make_float2(v0.x, v1.x);
        *(float2*)(dst + (size_t)(ie + 1) * HIDD + 2 * hp) =
            make_float2(v0.y, v1.y);
    }
}

// ---------------- reduce 16 partials ----------------
__global__ __launch_bounds__(256) void reduce_w_k(const float* __restrict__ wp,
                                                  float* __restrict__ w)
{
    int i4 = blockIdx.x * 256 + threadIdx.x;
    float4 s = ((const float4*)wp)[i4];
#pragma unroll
    for (int b = 1; b < NPART; b++) {
        float4 v = ((const float4*)(wp + (size_t)b * Nn * HIDD))[i4];
        s.x += v.x; s.y += v.y; s.z += v.z; s.w += v.w;
    }
    ((float4*)w)[i4] = s;
}

// ---------------- launch ----------------
extern "C" void kernel_launch(void* const* d_in, const int* in_sizes, int n_in,
                              void* d_out, int out_size)
{
    const float* app   = (const float*)d_in[0];
    const float* edges = (const float*)d_in[1];
    const float* We    = (const float*)d_in[2];
    const float* be    = (const float*)d_in[3];
    const float* Wq    = (const float*)d_in[4];
    const float* bq    = (const float*)d_in[5];
    const float* Wk    = (const float*)d_in[6];
    // d_in[7] = bk: per-row constant in S -> cancels in softmax
    const float* Wv    = (const float*)d_in[8];
    const float* bv    = (const float*)d_in[9];
    const float* Wo    = (const float*)d_in[10];
    const float* bo    = (const float*)d_in[11];
    float* out = (float*)d_out;

    float *F, *q, *qk, *S, *S2, *wp, *w, *agg;
    cudaGetSymbolAddress((void**)&F,   g_F);
    cudaGetSymbolAddress((void**)&q,   g_q);
    cudaGetSymbolAddress((void**)&qk,  g_qk);
    cudaGetSymbolAddress((void**)&S,   g_S);
    cudaGetSymbolAddress((void**)&S2,  g_S2);
    cudaGetSymbolAddress((void**)&wp,  g_wp);
    cudaGetSymbolAddress((void**)&w,   g_w);
    cudaGetSymbolAddress((void**)&agg, g_agg);

    // F and q in one launch (shared A)
    gemm_fq_k<<<dim3(12, Nn / 32), 256>>>(app, We + 6, Wq, be, bq, F, q);
    // qk = (q @ Wk) / sqrt(128)
    gemm_k<false><<<dim3(HIDD / 32, Nn / 32), 256>>>(
        q, AH, Wk, HIDD, nullptr, qk, HIDD, AH, 0.08838834764831845f);

    passA_k<<<dim3(Nn / 32, Nn / 16, 2), 128>>>(edges, We, F, qk, S, S2);
    softmax_k<<<Nn, 256>>>(S, S2);
    passB_k<<<dim3(Nn / 32, Nn / 8), 128>>>(edges, We, F, S, wp);
    reduce_w_k<<<Nn * HIDD / 4 / 256, 256>>>(wp, w);

    gemm_k<true><<<dim3(HIDD / 32, Nn / 32), 256>>>(
        w, HIDD, Wv, HIDD, bv, agg, HIDD, HIDD, 1.f);
    gemm_cat2_k<<<dim3(OUTD / 32, Nn / 32), 256>>>(app, agg, Wo, bo, out);
}

// round 8
// speedup vs baseline: 1.4769x; 1.1714x over previous
#include <cuda_runtime.h>
#include <cstddef>

typedef unsigned long long ull;

#define Nn   512
#define IND  256
#define HIDD 256
#define AH   128
#define OUTD 256
#define WELD 262   // IN_DIM + 6

// ---------------- scratch ----------------
__device__ float g_F[Nn * HIDD];
__device__ float g_q[Nn * AH];
__device__ float g_qk[Nn * HIDD];
__device__ float g_w[Nn * HIDD];
__device__ float g_agg[Nn * HIDD];

// ---------------- f32x2 helpers ----------------
__device__ __forceinline__ ull pack2(float lo, float hi) {
    ull r; asm("mov.b64 %0,{%1,%2};" : "=l"(r) : "f"(lo), "f"(hi)); return r;
}
__device__ __forceinline__ float2 unp2(ull x) {
    float2 f; asm("mov.b64 {%0,%1},%2;" : "=f"(f.x), "=f"(f.y) : "l"(x)); return f;
}
__device__ __forceinline__ ull fma2(ull a, ull b, ull c) {
    ull d; asm("fma.rn.f32x2 %0,%1,%2,%3;" : "=l"(d) : "l"(a), "l"(b), "l"(c)); return d;
}
__device__ __forceinline__ ull relu2(ull x) {
    ull r;
    asm("{.reg .f32 lo,hi;\n\t"
        "mov.b64 {lo,hi},%1;\n\t"
        "max.f32 lo,lo,0f00000000;\n\t"
        "max.f32 hi,hi,0f00000000;\n\t"
        "mov.b64 %0,{lo,hi};}" : "=l"(r) : "l"(x));
    return r;
}

// ---------------- small fp32 GEMM ----------------
template <bool TRANSB>
__global__ __launch_bounds__(256) void gemm_k(
    const float* __restrict__ A, int lda,
    const float* __restrict__ B, int ldb,
    const float* __restrict__ bias,
    float* __restrict__ C, int ldc,
    int K, float alpha)
{
    __shared__ float As[32][34];
    __shared__ float Bs[32][34];
    const int t = threadIdx.x;
    const int tx = t & 15, ty = t >> 4;
    const int mb = blockIdx.y * 32, nb = blockIdx.x * 32;
    float a00 = 0.f, a01 = 0.f, a10 = 0.f, a11 = 0.f;

    for (int k0 = 0; k0 < K; k0 += 32) {
#pragma unroll
        for (int r = 0; r < 4; r++) {
            int idx = t + r * 256;
            int p = idx >> 5, s = idx & 31;
            As[s][p] = A[(size_t)(mb + p) * lda + (k0 + s)];
            if (TRANSB)
                Bs[s][p] = B[(size_t)(nb + p) * ldb + (k0 + s)];
            else
                Bs[p][s] = B[(size_t)(k0 + p) * ldb + (nb + s)];
        }
        __syncthreads();
#pragma unroll
        for (int kk = 0; kk < 32; kk++) {
            float2 av = *(const float2*)&As[kk][ty * 2];
            float2 bv = *(const float2*)&Bs[kk][tx * 2];
            a00 = fmaf(av.x, bv.x, a00);
            a01 = fmaf(av.x, bv.y, a01);
            a10 = fmaf(av.y, bv.x, a10);
            a11 = fmaf(av.y, bv.y, a11);
        }
        __syncthreads();
    }

    int m = mb + ty * 2, n = nb + tx * 2;
    float b0 = bias ? bias[n] : 0.f;
    float b1 = bias ? bias[n + 1] : 0.f;
    C[(size_t)m * ldc + n]           = fmaf(alpha, a00, b0);
    C[(size_t)m * ldc + n + 1]       = fmaf(alpha, a01, b1);
    C[(size_t)(m + 1) * ldc + n]     = fmaf(alpha, a10, b0);
    C[(size_t)(m + 1) * ldc + n + 1] = fmaf(alpha, a11, b1);
}

// ---------------- fused F + q GEMM (shared A = app) ----------------
__global__ __launch_bounds__(256) void gemm_fq_k(
    const float* __restrict__ app,
    const float* __restrict__ We6,
    const float* __restrict__ Wq,
    const float* __restrict__ be,
    const float* __restrict__ bq,
    float* __restrict__ F,
    float* __restrict__ q)
{
    const bool isF = blockIdx.x < 8;
    const float* B    = isF ? We6 : Wq;
    const int    ldb  = isF ? WELD : IND;
    const float* bias = isF ? be : bq;
    float*       C    = isF ? F : q;
    const int    ldc  = isF ? HIDD : AH;
    const int    nb   = (isF ? blockIdx.x : blockIdx.x - 8) * 32;

    __shared__ float As[32][34];
    __shared__ float Bs[32][34];
    const int t = threadIdx.x;
    const int tx = t & 15, ty = t >> 4;
    const int mb = blockIdx.y * 32;
    float a00 = 0.f, a01 = 0.f, a10 = 0.f, a11 = 0.f;

    for (int k0 = 0; k0 < IND; k0 += 32) {
#pragma unroll
        for (int r = 0; r < 4; r++) {
            int idx = t + r * 256;
            int p = idx >> 5, s = idx & 31;
            As[s][p] = app[(size_t)(mb + p) * IND + (k0 + s)];
            Bs[s][p] = B[(size_t)(nb + p) * ldb + (k0 + s)];
        }
        __syncthreads();
#pragma unroll
        for (int kk = 0; kk < 32; kk++) {
            float2 av = *(const float2*)&As[kk][ty * 2];
            float2 bv = *(const float2*)&Bs[kk][tx * 2];
            a00 = fmaf(av.x, bv.x, a00);
            a01 = fmaf(av.x, bv.y, a01);
            a10 = fmaf(av.y, bv.x, a10);
            a11 = fmaf(av.y, bv.y, a11);
        }
        __syncthreads();
    }

    int m = mb + ty * 2, n = nb + tx * 2;
    C[(size_t)m * ldc + n]           = a00 + bias[n];
    C[(size_t)m * ldc + n + 1]       = a01 + bias[n + 1];
    C[(size_t)(m + 1) * ldc + n]     = a10 + bias[n];
    C[(size_t)(m + 1) * ldc + n + 1] = a11 + bias[n + 1];
}

// ---------------- concat-K output GEMM: C = relu([A1|A2] @ B^T + bias) --------
__global__ __launch_bounds__(256) void gemm_cat2_k(
    const float* __restrict__ A1,
    const float* __restrict__ A2,
    const float* __restrict__ B,
    const float* __restrict__ bias,
    float* __restrict__ C)
{
    __shared__ float As[32][34];
    __shared__ float Bs[32][34];
    const int t = threadIdx.x;
    const int tx = t & 15, ty = t >> 4;
    const int mb = blockIdx.y * 32, nb = blockIdx.x * 32;
    float a00 = 0.f, a01 = 0.f, a10 = 0.f, a11 = 0.f;

    for (int k0 = 0; k0 < 512; k0 += 32) {
        const float* Asrc = (k0 < 256) ? A1 : A2;
        const int koff = (k0 < 256) ? k0 : k0 - 256;
#pragma unroll
        for (int r = 0; r < 4; r++) {
            int idx = t + r * 256;
            int p = idx >> 5, s = idx & 31;
            As[s][p] = Asrc[(size_t)(mb + p) * 256 + koff + s];
            Bs[s][p] = B[(size_t)(nb + p) * 512 + k0 + s];
        }
        __syncthreads();
#pragma unroll
        for (int kk = 0; kk < 32; kk++) {
            float2 av = *(const float2*)&As[kk][ty * 2];
            float2 bv = *(const float2*)&Bs[kk][tx * 2];
            a00 = fmaf(av.x, bv.x, a00);
            a01 = fmaf(av.x, bv.y, a01);
            a10 = fmaf(av.y, bv.x, a10);
            a11 = fmaf(av.y, bv.y, a11);
        }
        __syncthreads();
    }

    int m = mb + ty * 2, n = nb + tx * 2;
    float b0 = bias[n], b1 = bias[n + 1];
    C[(size_t)m * OUTD + n]           = fmaxf(a00 + b0, 0.f);
    C[(size_t)m * OUTD + n + 1]       = fmaxf(a01 + b1, 0.f);
    C[(size_t)(m + 1) * OUTD + n]     = fmaxf(a10 + b0, 0.f);
    C[(size_t)(m + 1) * OUTD + n + 1] = fmaxf(a11 + b1, 0.f);
}

// ================ fused attention middle: 2 i-rows per block ===============
// w[i,h] = (1/l_i) * sum_j exp(s_ij) * E[i,j,h],  E = relu(F[j]+e(i,j)·We6)
// s_ij = sum_h qk[i,h]*E[i,j,h]  (qk pre-scaled; diag excluded; no-max exp)
// 256 threads = 8 warps. Warp w handles j = tau*8+w (tau=0..63). Lane l owns
// h-pairs {4l..4l+3} (h = 8l..8l+7): We/qk in regs, F via 2xLDG.128 from L2.
// h-reduction = 5 warp shuffles. Final 8-warp reduce via smem, once.
#define FU_SMEM ((6144 + 768 + 2048) * 8 + 64)

__global__ __launch_bounds__(256, 2) void fused_k(
    const float* __restrict__ edges,
    const float* __restrict__ We,
    const float* __restrict__ Fm,
    const float* __restrict__ qkm,
    float* __restrict__ wout)
{
    extern __shared__ __align__(16) ull smf[];
    ull*   e2    = smf;                 // [2][512][6] dup-packed edges (48KB)
    ull*   We2s  = e2 + 6144;           // [128 hp][6] dup... pair-packed (6KB)
    ull*   waccs = We2s + 768;          // [8 w][32 l][8 slot] (16KB)
    float* wl    = (float*)(waccs + 2048);  // [8 w][2 i]

    const int t = threadIdx.x;
    const int l = t & 31, w = t >> 5;
    const int ib = blockIdx.x * 2;

    // ---- stage edges for both i rows (contiguous, coalesced), dup-packed ----
    {
        const float* esrc = edges + (size_t)ib * (Nn * 6);
        for (int idx = t; idx < 2 * Nn * 6; idx += 256) {
            float v = esrc[idx];
            e2[idx] = pack2(v, v);
        }
    }
    // ---- stage We edge cols, pair-packed: We2s[hp*6+c] = (We[2hp,c],We[2hp+1,c])
    for (int idx = t; idx < 128 * 6; idx += 256) {
        int hp = idx / 6, c = idx - hp * 6;
        We2s[idx] = pack2(We[(size_t)(2 * hp) * WELD + c],
                          We[(size_t)(2 * hp + 1) * WELD + c]);
    }
    __syncthreads();

    // ---- per-lane register state ----
    ull W2[4][6];
#pragma unroll
    for (int k = 0; k < 4; k++) {
        int hp = 4 * l + k;
#pragma unroll
        for (int c = 0; c < 6; c++) W2[k][c] = We2s[hp * 6 + c];
    }
    ull qk2[2][4];
    {
        const ulonglong2* qa =
            (const ulonglong2*)(qkm + (size_t)ib * HIDD + 8 * l);
        const ulonglong2* qb =
            (const ulonglong2*)(qkm + (size_t)(ib + 1) * HIDD + 8 * l);
        ulonglong2 v0 = qa[0], v1 = qa[1];
        qk2[0][0] = v0.x; qk2[0][1] = v0.y; qk2[0][2] = v1.x; qk2[0][3] = v1.y;
        v0 = qb[0]; v1 = qb[1];
        qk2[1][0] = v0.x; qk2[1][1] = v0.y; qk2[1][2] = v1.x; qk2[1][3] = v1.y;
    }

    ull z = pack2(0.f, 0.f);
    ull acc[2][4] = {{z, z, z, z}, {z, z, z, z}};
    float lw0 = 0.f, lw1 = 0.f;

    // F prefetch for tau = 0
    ull Fc[4], Fn[4];
    {
        const ulonglong2* fp = (const ulonglong2*)(Fm + (size_t)w * HIDD + 8 * l);
        ulonglong2 v0 = fp[0], v1 = fp[1];
        Fc[0] = v0.x; Fc[1] = v0.y; Fc[2] = v1.x; Fc[3] = v1.y;
    }

    for (int tau = 0; tau < 64; tau++) {
        const int jj = tau * 8 + w;
        if (tau < 63) {
            const ulonglong2* fp =
                (const ulonglong2*)(Fm + (size_t)(jj + 8) * HIDD + 8 * l);
            ulonglong2 v0 = fp[0], v1 = fp[1];
            Fn[0] = v0.x; Fn[1] = v0.y; Fn[2] = v1.x; Fn[3] = v1.y;
        }
#pragma unroll
        for (int i = 0; i < 2; i++) {
            const ull* ep = e2 + (i * Nn + jj) * 6;        // broadcast reads
            ull e0 = ep[0], e1 = ep[1], e2v = ep[2];
            ull e3 = ep[3], e4 = ep[4], e5 = ep[5];
            ull g[4];
#pragma unroll
            for (int k = 0; k < 4; k++) {
                ull gg = fma2(e0, W2[k][0], Fc[k]);
                gg = fma2(e1, W2[k][1], gg);
                gg = fma2(e2v, W2[k][2], gg);
                gg = fma2(e3, W2[k][3], gg);
                gg = fma2(e4, W2[k][4], gg);
                gg = fma2(e5, W2[k][5], gg);
                g[k] = relu2(gg);
            }
            // score partial over owned 8 h's
            ull sd = fma2(qk2[i][0], g[0], z);
            sd = fma2(qk2[i][1], g[1], sd);
            sd = fma2(qk2[i][2], g[2], sd);
            sd = fma2(qk2[i][3], g[3], sd);
            float2 sv = unp2(sd);
            float s = sv.x + sv.y;
#pragma unroll
            for (int o = 16; o; o >>= 1)
                s += __shfl_xor_sync(0xffffffffu, s, o);
            float p = (jj == ib + i) ? 0.f : __expf(s);
            if (i == 0) lw0 += p; else lw1 += p;
            ull p2 = pack2(p, p);
#pragma unroll
            for (int k = 0; k < 4; k++)
                acc[i][k] = fma2(p2, g[k], acc[i][k]);
        }
#pragma unroll
        for (int k = 0; k < 4; k++) Fc[k] = Fn[k];
    }

    // ---- final cross-warp reduce ----
    ull* wb = waccs + (w * 32 + l) * 8;
#pragma unroll
    for (int k = 0; k < 4; k++) { wb[k] = acc[0][k]; wb[4 + k] = acc[1][k]; }
    if (l == 0) { wl[w * 2] = lw0; wl[w * 2 + 1] = lw1; }
    __syncthreads();
    {
        int i = t >> 7, hp = t & 127;
        int lo = hp >> 2, ko = hp & 3;
        float sx = 0.f, sy = 0.f, li = 0.f;
#pragma unroll
        for (int ww = 0; ww < 8; ww++) {
            float2 v = unp2(waccs[(ww * 32 + lo) * 8 + i * 4 + ko]);
            sx += v.x; sy += v.y;
            li += wl[ww * 2 + i];
        }
        float inv = 1.f / li;
        *(float2*)(wout + (size_t)(ib + i) * HIDD + 2 * hp) =
            make_float2(sx * inv, sy * inv);
    }
}

// ---------------- launch ----------------
extern "C" void kernel_launch(void* const* d_in, const int* in_sizes, int n_in,
                              void* d_out, int out_size)
{
    const float* app   = (const float*)d_in[0];
    const float* edges = (const float*)d_in[1];
    const float* We    = (const float*)d_in[2];
    const float* be    = (const float*)d_in[3];
    const float* Wq    = (const float*)d_in[4];
    const float* bq    = (const float*)d_in[5];
    const float* Wk    = (const float*)d_in[6];
    // d_in[7] = bk: contributes q·bk, constant per row -> cancels in softmax
    const float* Wv    = (const float*)d_in[8];
    const float* bv    = (const float*)d_in[9];
    const float* Wo    = (const float*)d_in[10];
    const float* bo    = (const float*)d_in[11];
    float* out = (float*)d_out;

    float *F, *q, *qk, *w, *agg;
    cudaGetSymbolAddress((void**)&F,   g_F);
    cudaGetSymbolAddress((void**)&q,   g_q);
    cudaGetSymbolAddress((void**)&qk,  g_qk);
    cudaGetSymbolAddress((void**)&w,   g_w);
    cudaGetSymbolAddress((void**)&agg, g_agg);

    cudaFuncSetAttribute(fused_k, cudaFuncAttributeMaxDynamicSharedMemorySize,
                         FU_SMEM);

    // F and q in one launch (shared A)
    gemm_fq_k<<<dim3(12, Nn / 32), 256>>>(app, We + 6, Wq, be, bq, F, q);
    // qk = (q @ Wk) / sqrt(128)
    gemm_k<false><<<dim3(HIDD / 32, Nn / 32), 256>>>(
        q, AH, Wk, HIDD, nullptr, qk, HIDD, AH, 0.08838834764831845f);

    // fused E-build + scores + softmax + aggregation
    fused_k<<<Nn / 2, 256, FU_SMEM>>>(edges, We, F, qk, w);

    // agg = w @ Wv^T + bv
    gemm_k<true><<<dim3(HIDD / 32, Nn / 32), 256>>>(
        w, HIDD, Wv, HIDD, bv, agg, HIDD, HIDD, 1.f);
    // out = relu([app|agg] @ Wo^T + bo)
    gemm_cat2_k<<<dim3(OUTD / 32, Nn / 32), 256>>>(app, agg, Wo, bo, out);
}